// round 13
// baseline (speedup 1.0000x reference)
#include <cuda_runtime.h>
#include <cuda_bf16.h>
#include <math.h>
#include <stdint.h>

#define BSZ   8
#define C1    256
#define C2    128
#define MID   256
#define NPIX  4096
#define PB    (MID*NPIX)
#define TOT   ((size_t)BSZ*PB)
#define DD    32
#define NSPLIT 8
#define HROWS 33
#define HSZ   (HROWS * 64)

__device__ __forceinline__ uint32_t smem_u32(const void* p) {
    uint32_t a;
    asm("{ .reg .u64 t; cvta.to.shared.u64 t, %1; cvt.u32.u64 %0, t; }" : "=r"(a) : "l"(p));
    return a;
}

#define CP16(sa, ga) \
    asm volatile("cp.async.ca.shared.global [%0], [%1], 16;" :: "r"(sa), "l"(ga) : "memory")
#define CP_COMMIT() asm volatile("cp.async.commit_group;" ::: "memory")
#define CP_WAIT1()  asm volatile("cp.async.wait_group 1;" ::: "memory")

#define LDSM4(r0, r1, r2, r3, a) \
    asm volatile("ldmatrix.sync.aligned.m8n8.x4.shared.b16 {%0,%1,%2,%3}, [%4];" \
        : "=r"(r0), "=r"(r1), "=r"(r2), "=r"(r3) : "r"(a))

#define MMA16816(c, a, b0, b1) \
    asm volatile("mma.sync.aligned.m16n8k16.row.col.f32.bf16.bf16.f32 " \
        "{%0,%1,%2,%3}, {%4,%5,%6,%7}, {%8,%9}, {%0,%1,%2,%3};" \
        : "+f"((c)[0]), "+f"((c)[1]), "+f"((c)[2]), "+f"((c)[3]) \
        : "r"((a)[0]), "r"((a)[1]), "r"((a)[2]), "r"((a)[3]), "r"(b0), "r"(b1))

__device__ float g_pool[22ull * TOT];

struct Aux {
    cudaStream_t s1, s2;
    cudaEvent_t ev[10];
    Aux() {
        cudaStreamCreateWithFlags(&s1, cudaStreamNonBlocking);
        cudaStreamCreateWithFlags(&s2, cudaStreamNonBlocking);
        for (int i = 0; i < 10; ++i)
            cudaEventCreateWithFlags(&ev[i], cudaEventDisableTiming);
    }
};
static Aux g_aux;

// ---------------------------------------------------------------------------
// Split-bf16 tensor-core GEMM:  Y = scale*(A @ B^T) + bias
// ---------------------------------------------------------------------------
#define ST_BYTES 49152
#define G_SMEM   (3 * ST_BYTES)

__global__ __launch_bounds__(256, 1)
void mma_gemm(const __nv_bfloat16* __restrict__ Ah, const __nv_bfloat16* __restrict__ Al,
              size_t aStride,
              const __nv_bfloat16* __restrict__ Bh, const __nv_bfloat16* __restrict__ Bl,
              size_t bStride,
              const float* __restrict__ bias, float* __restrict__ Y,
              size_t yStride, size_t partStride,
              int Kstride, int Klen, int N, float scale, int NS)
{
    extern __shared__ __nv_bfloat16 dynsm[];
    const uint32_t smBase = smem_u32(dynsm);
    const int t = threadIdx.x, wid = t >> 5, lid = t & 31;
    const int wm = wid & 1, wn = wid >> 1;
    const int z = blockIdx.z;
    const int b = z / NS, s = z % NS;
    const int kBeg = s * Klen;
    const int m0 = blockIdx.y * 128, n0 = blockIdx.x * 256;

    const __nv_bfloat16* P[4];
    P[0] = Ah + (size_t)b * aStride + (size_t)m0 * Kstride + kBeg;
    P[1] = Al + (size_t)b * aStride + (size_t)m0 * Kstride + kBeg;
    P[2] = Bh + (size_t)b * bStride + (size_t)n0 * Kstride + kBeg;
    P[3] = Bl + (size_t)b * bStride + (size_t)n0 * Kstride + kBeg;
    float* Yp = Y + (size_t)b * yStride + (size_t)s * partStride;

    const int NC = Klen >> 5;

    int lrow[4], lc[4]; uint32_t lso[4];
#pragma unroll
    for (int r = 0; r < 4; ++r) {
        int q = t + 256 * r;
        lrow[r] = q >> 2; lc[r] = q & 3;
        lso[r] = lrow[r] * 64 + ((lc[r] ^ ((lrow[r] >> 1) & 3)) * 16);
    }

    const int lj = lid >> 3, lr = lid & 7;
    uint32_t aAddr[4], bAddr[4];
#pragma unroll
    for (int i = 0; i < 4; ++i) {
        int row = wm * 64 + i * 16 + ((lj & 1) << 3) + lr;
        int c = (lj >> 1) ^ ((row >> 1) & 3);
        aAddr[i] = smBase + row * 64 + c * 16;
    }
#pragma unroll
    for (int p = 0; p < 4; ++p) {
        int n = wn * 64 + p * 16 + ((lj >> 1) << 3) + lr;
        int c = (lj & 1) ^ ((n >> 1) & 3);
        bAddr[p] = smBase + 16384 + n * 64 + c * 16;
    }

    float acc[4][8][4];
#pragma unroll
    for (int i = 0; i < 4; ++i)
#pragma unroll
        for (int j = 0; j < 8; ++j)
#pragma unroll
            for (int e = 0; e < 4; ++e) acc[i][j][e] = 0.f;

#define LOADSTAGE(CH, SLOT) do {                                              \
        int kc_ = (CH) << 5;                                                  \
        uint32_t so_ = (uint32_t)(SLOT) * ST_BYTES;                           \
        _Pragma("unroll")                                                     \
        for (int pl_ = 0; pl_ < 2; ++pl_) {                                   \
            const __nv_bfloat16* src_ = P[pl_] + kc_;                         \
            uint32_t dst_ = smBase + so_ + pl_ * 8192;                        \
            _Pragma("unroll")                                                 \
            for (int r_ = 0; r_ < 2; ++r_)                                    \
                CP16(dst_ + lso[r_], src_ + (size_t)lrow[r_] * Kstride + lc[r_] * 8); \
        }                                                                     \
        _Pragma("unroll")                                                     \
        for (int pl_ = 2; pl_ < 4; ++pl_) {                                   \
            const __nv_bfloat16* src_ = P[pl_] + kc_;                         \
            uint32_t dst_ = smBase + so_ + 16384 + (pl_ - 2) * 16384;         \
            _Pragma("unroll")                                                 \
            for (int r_ = 0; r_ < 4; ++r_)                                    \
                CP16(dst_ + lso[r_], src_ + (size_t)lrow[r_] * Kstride + lc[r_] * 8); \
        }                                                                     \
    } while (0)

    LOADSTAGE(0, 0); CP_COMMIT();
    LOADSTAGE(1, 1); CP_COMMIT();

    for (int ch = 0; ch < NC; ++ch) {
        CP_WAIT1();
        __syncthreads();
        int nxt = ch + 2;
        if (nxt < NC) LOADSTAGE(nxt, nxt % 3);
        CP_COMMIT();

        const uint32_t stoff = (uint32_t)(ch % 3) * ST_BYTES;
#pragma unroll
        for (int kt = 0; kt < 2; ++kt) {
            const uint32_t kx = kt ? 32u : 0u;
            uint32_t aH[4][4], bH[4][4], aL[4][4], bL[4][4];
#pragma unroll
            for (int i = 0; i < 4; ++i)
                LDSM4(aH[i][0], aH[i][1], aH[i][2], aH[i][3], (aAddr[i] + stoff) ^ kx);
#pragma unroll
            for (int p = 0; p < 4; ++p)
                LDSM4(bH[p][0], bH[p][1], bH[p][2], bH[p][3], (bAddr[p] + stoff) ^ kx);
#pragma unroll
            for (int i = 0; i < 4; ++i)
                LDSM4(aL[i][0], aL[i][1], aL[i][2], aL[i][3], (aAddr[i] + stoff + 8192) ^ kx);
#pragma unroll
            for (int p = 0; p < 4; ++p)
                LDSM4(bL[p][0], bL[p][1], bL[p][2], bL[p][3], (bAddr[p] + stoff + 16384) ^ kx);
#pragma unroll
            for (int i = 0; i < 4; ++i)
#pragma unroll
                for (int j = 0; j < 8; ++j)
                    MMA16816(acc[i][j], aH[i], bH[j >> 1][(j & 1) * 2], bH[j >> 1][(j & 1) * 2 + 1]);
#pragma unroll
            for (int i = 0; i < 4; ++i)
#pragma unroll
                for (int j = 0; j < 8; ++j)
                    MMA16816(acc[i][j], aL[i], bH[j >> 1][(j & 1) * 2], bH[j >> 1][(j & 1) * 2 + 1]);
#pragma unroll
            for (int i = 0; i < 4; ++i)
#pragma unroll
                for (int j = 0; j < 8; ++j)
                    MMA16816(acc[i][j], aH[i], bL[j >> 1][(j & 1) * 2], bL[j >> 1][(j & 1) * 2 + 1]);
        }
    }
#undef LOADSTAGE

    const int groupID = lid >> 2, tid4 = lid & 3;
#pragma unroll
    for (int i = 0; i < 4; ++i) {
        int r0 = m0 + wm * 64 + i * 16 + groupID;
        int r1 = r0 + 8;
        float bv0 = bias ? bias[r0] : 0.f;
        float bv1 = bias ? bias[r1] : 0.f;
        float* y0 = Yp + (size_t)r0 * N + n0 + wn * 64 + tid4 * 2;
        float* y1 = Yp + (size_t)r1 * N + n0 + wn * 64 + tid4 * 2;
#pragma unroll
        for (int j = 0; j < 8; ++j) {
            *(float2*)(y0 + j * 8) = make_float2(fmaf(acc[i][j][0], scale, bv0),
                                                 fmaf(acc[i][j][1], scale, bv0));
            *(float2*)(y1 + j * 8) = make_float2(fmaf(acc[i][j][2], scale, bv1),
                                                 fmaf(acc[i][j][3], scale, bv1));
        }
    }
}

// ---------------------------------------------------------------------------
// Radix-8x8 FFT machinery
// ---------------------------------------------------------------------------
__device__ __forceinline__ float2 cmulf(float2 a, float2 b) {
    return make_float2(a.x * b.x - a.y * b.y, a.x * b.y + a.y * b.x);
}

template<int S>
__device__ __forceinline__ void fft8(float2 v[8])
{
    const float C0 = 0.70710678118654752f;
    const float SG = (float)S;
    float2 a0 = make_float2(v[0].x + v[4].x, v[0].y + v[4].y);
    float2 a1 = make_float2(v[1].x + v[5].x, v[1].y + v[5].y);
    float2 a2 = make_float2(v[2].x + v[6].x, v[2].y + v[6].y);
    float2 a3 = make_float2(v[3].x + v[7].x, v[3].y + v[7].y);
    float2 b0 = make_float2(v[0].x - v[4].x, v[0].y - v[4].y);
    float2 b1 = make_float2(v[1].x - v[5].x, v[1].y - v[5].y);
    float2 b2 = make_float2(v[2].x - v[6].x, v[2].y - v[6].y);
    float2 b3 = make_float2(v[3].x - v[7].x, v[3].y - v[7].y);
    float2 t1 = make_float2(C0 * (b1.x - SG * b1.y), C0 * (SG * b1.x + b1.y));
    float2 t2 = make_float2(-SG * b2.y, SG * b2.x);
    float2 t3 = make_float2(C0 * (-b3.x - SG * b3.y), C0 * (SG * b3.x - b3.y));
    float2 c0 = make_float2(a0.x + a2.x, a0.y + a2.y);
    float2 c1 = make_float2(a1.x + a3.x, a1.y + a3.y);
    float2 d0 = make_float2(a0.x - a2.x, a0.y - a2.y);
    float2 e0 = make_float2(a1.x - a3.x, a1.y - a3.y);
    float2 d1 = make_float2(-SG * e0.y, SG * e0.x);
    float2 c2 = make_float2(b0.x + t2.x, b0.y + t2.y);
    float2 c3 = make_float2(t1.x + t3.x, t1.y + t3.y);
    float2 d2 = make_float2(b0.x - t2.x, b0.y - t2.y);
    float2 e1 = make_float2(t1.x - t3.x, t1.y - t3.y);
    float2 d3 = make_float2(-SG * e1.y, SG * e1.x);
    v[0] = make_float2(c0.x + c1.x, c0.y + c1.y);
    v[1] = make_float2(c2.x + c3.x, c2.y + c3.y);
    v[2] = make_float2(d0.x + d1.x, d0.y + d1.y);
    v[3] = make_float2(d2.x + d3.x, d2.y + d3.y);
    v[4] = make_float2(c0.x - c1.x, c0.y - c1.y);
    v[5] = make_float2(c2.x - c3.x, c2.y - c3.y);
    v[6] = make_float2(d0.x - d1.x, d0.y - d1.y);
    v[7] = make_float2(d2.x - d3.x, d2.y - d3.y);
}

template<int S>
__device__ __forceinline__ void fftpass(float2* bin, float2* bout, const float2* tw, int t)
{
    const int r = t >> 2, q = t & 3;
    const int rb = r * 65;
    float2 g[2][8];
#pragma unroll
    for (int gi = 0; gi < 2; ++gi) {
        int bcol = q + 4 * gi;
#pragma unroll
        for (int a = 0; a < 8; ++a) g[gi][a] = bin[rb + 8 * a + bcol];
        fft8<S>(g[gi]);
#pragma unroll
        for (int k1 = 0; k1 < 8; ++k1) g[gi][k1] = cmulf(g[gi][k1], tw[bcol * 8 + k1]);
    }
#pragma unroll
    for (int gi = 0; gi < 2; ++gi) {
        int bcol = q + 4 * gi;
#pragma unroll
        for (int k1 = 0; k1 < 8; ++k1) bin[rb + k1 * 8 + bcol] = g[gi][k1];
    }
    __syncwarp();
#pragma unroll
    for (int gi = 0; gi < 2; ++gi) {
        int k1 = q + 4 * gi;
        float2 h[8];
#pragma unroll
        for (int bcol = 0; bcol < 8; ++bcol) h[bcol] = bin[rb + k1 * 8 + bcol];
        fft8<S>(h);
#pragma unroll
        for (int k2 = 0; k2 < 8; ++k2) bout[(k1 + 8 * k2) * 65 + r] = h[k2];
    }
}

#define FFT_SMEM ((2 * 64 * 65 + 64) * 8)
#define DW_SMEM  (FFT_SMEM + 64 * 65 * 4)

__global__ void fft2_dw_kernel(const float* __restrict__ pre, size_t preStride,
                               const float* __restrict__ wt, const float* __restrict__ bs,
                               __nv_bfloat16* __restrict__ oh, __nv_bfloat16* __restrict__ ol,
                               int rev, float2* __restrict__ Xout)
{
    extern __shared__ float2 fsm[];
    float2* bufA = fsm;
    float2* bufB = fsm + 64 * 65;
    float2* tw   = fsm + 2 * 64 * 65;
    float*  xin  = (float*)(fsm + 2 * 64 * 65 + 64);
    int t = threadIdx.x;
    int img = blockIdx.x;
    int c = img & 255;
    if (t < 64) {
        int bcol = t >> 3, k1 = t & 7;
        float sn, cs; sincospif(-(float)(bcol * k1) / 32.0f, &sn, &cs);
        tw[t] = make_float2(cs, sn);
    }
    const float* xi = pre + (size_t)(img >> 8) * preStride + ((size_t)c << 12);
    for (int i = t; i < 4096; i += 256) xin[(i >> 6) * 65 + (i & 63)] = xi[i];
    const float* wp = wt + c * 9;
    float k0 = wp[0], k1 = wp[1], k2 = wp[2], k3 = wp[3], k4 = wp[4],
          k5 = wp[5], k6 = wp[6], k7 = wp[7], k8 = wp[8];
    float bv = bs[c];
    __syncthreads();
    for (int i = t; i < 4096; i += 256) {
        int h = i >> 6, w = i & 63;
        const float* row = xin + h * 65;
        float s = bv + k4 * row[w];
        bool ht = h > 0, hb = h < 63, wl = w > 0, wr = w < 63;
        if (ht) {
            const float* ru = row - 65;
            s += k1 * ru[w];
            if (wl) s += k0 * ru[w - 1];
            if (wr) s += k2 * ru[w + 1];
        }
        if (wl) s += k3 * row[w - 1];
        if (wr) s += k5 * row[w + 1];
        if (hb) {
            const float* rd = row + 65;
            s += k7 * rd[w];
            if (wl) s += k6 * rd[w - 1];
            if (wr) s += k8 * rd[w + 1];
        }
        bufA[h * 65 + w] = make_float2(s, 0.f);
        if (oh) {
            size_t base = (size_t)img << 12;
            int oi = rev ? ((((64 - h) & 63) << 6) | ((64 - w) & 63)) : i;
            __nv_bfloat16 hh = __float2bfloat16(s);
            oh[base + oi] = hh;
            ol[base + oi] = __float2bfloat16(s - __bfloat162float(hh));
        }
    }
    __syncthreads();
    fftpass<-1>(bufA, bufB, tw, t);
    __syncthreads();
    fftpass<-1>(bufB, bufA, tw, t);
    __syncthreads();
    float2* o = Xout + (size_t)blockIdx.x * HSZ;
    for (int i = t; i < HSZ; i += 256)
        o[i] = bufA[(i >> 6) * 65 + (i & 63)];
}

__global__ void ifft2_prod_kernel(const float2* __restrict__ FQ, const float2* __restrict__ FK,
                                  float* __restrict__ out)
{
    extern __shared__ float2 fsm[];
    float2* bufA = fsm;
    float2* bufB = fsm + 64 * 65;
    float2* tw   = fsm + 2 * 64 * 65;
    int t = threadIdx.x;
    if (t < 64) {
        int bcol = t >> 3, k1 = t & 7;
        float sn, cs; sincospif((float)(bcol * k1) / 32.0f, &sn, &cs);
        tw[t] = make_float2(cs, sn);
    }
    const float2* q = FQ + (size_t)blockIdx.x * HSZ;
    const float2* kk = FK + (size_t)blockIdx.x * HSZ;
    for (int i = t; i < HSZ; i += 256) {
        float2 a = q[i], b = kk[i];
        bufA[(i >> 6) * 65 + (i & 63)] =
            make_float2(a.x * b.x - a.y * b.y, a.x * b.y + a.y * b.x);
    }
    __syncthreads();
    for (int i = t; i < 31 * 64; i += 256) {
        int u = 33 + (i >> 6), v = i & 63;
        float2 m = bufA[(64 - u) * 65 + ((64 - v) & 63)];
        bufA[u * 65 + v] = make_float2(m.x, -m.y);
    }
    __syncthreads();
    fftpass<1>(bufA, bufB, tw, t);
    __syncthreads();
    fftpass<1>(bufB, bufA, tw, t);
    __syncthreads();
    float* o = out + (size_t)blockIdx.x * 4096;
    for (int i = t; i < 4096; i += 256)
        o[i] = bufA[(i >> 6) * 65 + (i & 63)].x * (1.0f / 4096.0f);
}

// ---------------------------------------------------------------------------
__global__ void convW_kernel(
    const float* __restrict__ wr, const float* __restrict__ wn,
    const float* __restrict__ pq, const float* __restrict__ pk, const float* __restrict__ pv,
    const float* __restrict__ ow,
    const float* __restrict__ pqb, const float* __restrict__ pkb, const float* __restrict__ pvb,
    __nv_bfloat16* wrh, __nv_bfloat16* wrl, __nv_bfloat16* wnh, __nv_bfloat16* wnl,
    __nv_bfloat16* wqh, __nv_bfloat16* wql, __nv_bfloat16* owh, __nv_bfloat16* owl,
    float* qkvb)
{
    int i = blockIdx.x * 256 + threadIdx.x;
    if (i < 65536) {
        float x = wr[i]; __nv_bfloat16 h = __float2bfloat16(x);
        wrh[i] = h; wrl[i] = __float2bfloat16(x - __bfloat162float(h));
    } else if (i < 98304) {
        int j = i - 65536;
        float x = wn[j]; __nv_bfloat16 h = __float2bfloat16(x);
        wnh[j] = h; wnl[j] = __float2bfloat16(x - __bfloat162float(h));
    } else if (i < 294912) {
        int j = i - 98304;
        const float* s3 = (j < 65536) ? pq : (j < 131072) ? pk : pv;
        float x = s3[j & 65535]; __nv_bfloat16 h = __float2bfloat16(x);
        wqh[j] = h; wql[j] = __float2bfloat16(x - __bfloat162float(h));
    } else if (i < 360448) {
        int j = i - 294912;
        float x = ow[j]; __nv_bfloat16 h = __float2bfloat16(x);
        owh[j] = h; owl[j] = __float2bfloat16(x - __bfloat162float(h));
    } else if (i < 361216) {
        int j = i - 360448;
        qkvb[j] = (j < 256) ? pqb[j] : (j < 512) ? pkb[j - 256] : pvb[j - 512];
    }
}

// packed-store transpose: fp32 [R][C] -> split-bf16 [C][R], 2 bf16 per STG.32
__global__ void convT_kernel(const float* __restrict__ in,
                             __nv_bfloat16* __restrict__ oh, __nv_bfloat16* __restrict__ ol,
                             int R, int C)
{
    __shared__ float tile[32][33];
    int b = blockIdx.z;
    const float* ip = in + (size_t)b * R * C;
    uint32_t* ohp = (uint32_t*)(oh + (size_t)b * R * C);
    uint32_t* olp = (uint32_t*)(ol + (size_t)b * R * C);
    int c0 = blockIdx.x * 32, r0 = blockIdx.y * 32;
    int tx = threadIdx.x, ty = threadIdx.y;   // (16,16)
#pragma unroll
    for (int j = 0; j < 2; ++j) {
        int row = ty + 16 * j;
        float2 v = *(const float2*)&ip[(size_t)(r0 + row) * C + c0 + 2 * tx];
        tile[row][2 * tx]     = v.x;
        tile[row][2 * tx + 1] = v.y;
    }
    __syncthreads();
#pragma unroll
    for (int j = 0; j < 2; ++j) {
        int cc = ty + 16 * j;
        float a = tile[2 * tx][cc], bv = tile[2 * tx + 1][cc];
        __nv_bfloat16 ha = __float2bfloat16(a), hb = __float2bfloat16(bv);
        __nv_bfloat16 la = __float2bfloat16(a - __bfloat162float(ha));
        __nv_bfloat16 lb = __float2bfloat16(bv - __bfloat162float(hb));
        size_t o = ((size_t)(c0 + cc) * R + r0 + 2 * tx) >> 1;
        ohp[o] = ((uint32_t)__bfloat16_as_ushort(hb) << 16) | __bfloat16_as_ushort(ha);
        olp[o] = ((uint32_t)__bfloat16_as_ushort(lb) << 16) | __bfloat16_as_ushort(la);
    }
}

// ---------------------------------------------------------------------------
__global__ void meanX_kernel(const float* __restrict__ x1, const float* __restrict__ x2,
                             float* __restrict__ m1, float* __restrict__ m2)
{
    __shared__ float red[256];
    int img = blockIdx.x, t = threadIdx.x;
    const float* src; float* dst; int idx;
    if (img < BSZ * C1) { src = x1 + (size_t)img * NPIX; dst = m1; idx = img; }
    else { idx = img - BSZ * C1; src = x2 + (size_t)idx * NPIX; dst = m2; }
    float s = 0.f;
    for (int i = t; i < NPIX; i += 256) s += src[i];
    red[t] = s; __syncthreads();
    for (int st = 128; st > 0; st >>= 1) {
        if (t < st) red[t] += red[t + st];
        __syncthreads();
    }
    if (t == 0) dst[idx] = red[0] * (1.0f / NPIX);
}

__global__ void pooledmlp_kernel(const float* __restrict__ m1, const float* __restrict__ m2,
                                 const float* __restrict__ wr, const float* __restrict__ br,
                                 const float* __restrict__ wn, const float* __restrict__ bn,
                                 const float* __restrict__ w1, const float* __restrict__ w2,
                                 float* __restrict__ a0out, float* __restrict__ a1out)
{
    __shared__ float pooled[MID];
    __shared__ float hs[DD];
    int b = blockIdx.x, t = threadIdx.x;
    {
        int c = t;
        float s = br[c] + bn[c];
        const float* wrow = wr + c * C1;
        const float* m1b = m1 + b * C1;
#pragma unroll 8
        for (int i = 0; i < C1; ++i) s += wrow[i] * m1b[i];
        const float* nrow = wn + c * C2;
        const float* m2b = m2 + b * C2;
#pragma unroll 8
        for (int j = 0; j < C2; ++j) s += nrow[j] * m2b[j];
        pooled[c] = s;
    }
    __syncthreads();
    {
        int d = t >> 3, ln = t & 7;
        float s = 0.f;
        for (int c = ln; c < MID; c += 8) s += pooled[c] * w1[d * MID + c];
#pragma unroll
        for (int k = 4; k > 0; k >>= 1) s += __shfl_down_sync(0xffffffffu, s, k, 8);
        if (ln == 0) hs[d] = fmaxf(s, 0.f);
    }
    __syncthreads();
    {
        int c = t;
        float a0 = 0.f, a1 = 0.f;
#pragma unroll
        for (int d = 0; d < DD; ++d) {
            float hv = hs[d];
            a0 += hv * w2[c * DD + d];
            a1 += hv * w2[(MID + c) * DD + d];
        }
        float m = fmaxf(a0, a1);
        float e0 = expf(a0 - m), e1 = expf(a1 - m);
        float inv = 1.0f / (e0 + e1);
        a0out[b * MID + c] = e0 * inv;
        a1out[b * MID + c] = e1 * inv;
    }
}

__global__ void blendT_kernel(const float* __restrict__ FR, const float* __restrict__ FN,
                              const float* __restrict__ w0, const float* __restrict__ w1,
                              float* __restrict__ Fw,
                              __nv_bfloat16* __restrict__ oh, __nv_bfloat16* __restrict__ ol)
{
    __shared__ float tile[32][33];
    int b = blockIdx.z;
    int p0 = blockIdx.x * 32, c0 = blockIdx.y * 32;
    int tx = threadIdx.x, ty = threadIdx.y;
#pragma unroll
    for (int j = 0; j < 4; ++j) {
        int c = c0 + ty + 8 * j;
        size_t idx = (size_t)b * PB + (size_t)c * NPIX + p0 + tx;
        float v = w0[b * MID + c] * FR[idx] + w1[b * MID + c] * FN[idx];
        Fw[idx] = v;
        tile[ty + 8 * j][tx] = v;
    }
    __syncthreads();
#pragma unroll
    for (int j = 0; j < 4; ++j) {
        float x = tile[tx][ty + 8 * j];
        __nv_bfloat16 h = __float2bfloat16(x);
        size_t o = (size_t)b * PB + (size_t)(p0 + ty + 8 * j) * MID + c0 + tx;
        oh[o] = h;
        ol[o] = __float2bfloat16(x - __bfloat162float(h));
    }
}

__global__ void dwconv3x3_kernel(const float* __restrict__ x, size_t preStride,
                                 const float* __restrict__ wt,
                                 const float* __restrict__ bs, float* __restrict__ y)
{
    __shared__ float xs[64][65];
    int img = blockIdx.x;
    int c = img & 255;
    const float* xi = x + (size_t)(img >> 8) * preStride + ((size_t)c << 12);
    for (int i = threadIdx.x; i < NPIX; i += 256) xs[i >> 6][i & 63] = xi[i];
    const float* wp = wt + c * 9;
    float k0 = wp[0], k1 = wp[1], k2 = wp[2], k3 = wp[3], k4 = wp[4],
          k5 = wp[5], k6 = wp[6], k7 = wp[7], k8 = wp[8];
    float bv = bs[c];
    __syncthreads();
    for (int i = threadIdx.x; i < NPIX; i += 256) {
        int h = i >> 6, w = i & 63;
        float s = bv + k4 * xs[h][w];
        bool ht = h > 0, hb = h < 63, wl = w > 0, wr = w < 63;
        if (ht) {
            s += k1 * xs[h - 1][w];
            if (wl) s += k0 * xs[h - 1][w - 1];
            if (wr) s += k2 * xs[h - 1][w + 1];
        }
        if (wl) s += k3 * xs[h][w - 1];
        if (wr) s += k5 * xs[h][w + 1];
        if (hb) {
            s += k7 * xs[h + 1][w];
            if (wl) s += k6 * xs[h + 1][w - 1];
            if (wr) s += k8 * xs[h + 1][w + 1];
        }
        y[((size_t)img << 12) + i] = s;
    }
}

__global__ void softmax_kernel(const float* __restrict__ attnP,
                               __nv_bfloat16* __restrict__ ah, __nv_bfloat16* __restrict__ al,
                               const float* __restrict__ alpha)
{
    __shared__ float red[256];
    int row = blockIdx.x, t = threadIdx.x;
    float v = 0.f;
#pragma unroll
    for (int s = 0; s < NSPLIT; ++s)
        v += attnP[(size_t)s * (BSZ * 65536) + (size_t)row * 256 + t];
    float inva = 1.0f / (*alpha);
    v = fabsf(v) * inva;
    red[t] = v; __syncthreads();
    for (int s = 128; s > 0; s >>= 1) {
        if (t < s) red[t] = fmaxf(red[t], red[t + s]);
        __syncthreads();
    }
    float m = red[0]; __syncthreads();
    float e = expf(v - m);
    red[t] = e; __syncthreads();
    for (int s = 128; s > 0; s >>= 1) {
        if (t < s) red[t] += red[t + s];
        __syncthreads();
    }
    float val = e / red[0];
    __nv_bfloat16 h = __float2bfloat16(val);
    ah[(size_t)row * 256 + t] = h;
    al[(size_t)row * 256 + t] = __float2bfloat16(val - __bfloat162float(h));
}

__global__ void fuseT_kernel(const __nv_bfloat16* __restrict__ Qh,
                             const __nv_bfloat16* __restrict__ Ql,
                             const float* __restrict__ cfr,
                             const float* __restrict__ V, const float* __restrict__ Fw,
                             const float* __restrict__ lambd, const float* __restrict__ beta,
                             __nv_bfloat16* __restrict__ oh, __nv_bfloat16* __restrict__ ol)
{
    __shared__ float tile[32][33];
    int b = blockIdx.z;
    int p0 = blockIdx.x * 32, c0 = blockIdx.y * 32;
    int tx = threadIdx.x, ty = threadIdx.y;
    float l = *lambd, be = *beta;
#pragma unroll
    for (int j = 0; j < 4; ++j) {
        size_t idx = (size_t)b * PB + (size_t)(c0 + ty + 8 * j) * NPIX + p0 + tx;
        float q = __bfloat162float(Qh[idx]) + __bfloat162float(Ql[idx]);
        float c = cfr[idx], v = V[idx], f = Fw[idx];
        float freq_out = q * c + v - l * v * c;
        tile[ty + 8 * j][tx] = be * freq_out + (1.0f - be) * f;
    }
    __syncthreads();
#pragma unroll
    for (int j = 0; j < 4; ++j) {
        float x = tile[tx][ty + 8 * j];
        __nv_bfloat16 h = __float2bfloat16(x);
        size_t o = (size_t)b * PB + (size_t)(p0 + ty + 8 * j) * MID + c0 + tx;
        oh[o] = h;
        ol[o] = __float2bfloat16(x - __bfloat162float(h));
    }
}

// ---------------------------------------------------------------------------
extern "C" void kernel_launch(void* const* d_in, const int* in_sizes, int n_in,
                              void* d_out, int out_size)
{
    const float* x1       = (const float*)d_in[0];
    const float* x2       = (const float*)d_in[1];
    const float* conv_r_w = (const float*)d_in[2];
    const float* conv_r_b = (const float*)d_in[3];
    const float* conv_n_w = (const float*)d_in[4];
    const float* conv_n_b = (const float*)d_in[5];
    const float* mlp_w1   = (const float*)d_in[6];
    const float* mlp_w2   = (const float*)d_in[7];
    const float* pq_w     = (const float*)d_in[8];
    const float* pq_b     = (const float*)d_in[9];
    const float* dq_w     = (const float*)d_in[10];
    const float* dq_b     = (const float*)d_in[11];
    const float* pk_w     = (const float*)d_in[12];
    const float* pk_b     = (const float*)d_in[13];
    const float* dk_w     = (const float*)d_in[14];
    const float* dk_b     = (const float*)d_in[15];
    const float* pv_w     = (const float*)d_in[16];
    const float* pv_b     = (const float*)d_in[17];
    const float* dv_w     = (const float*)d_in[18];
    const float* dv_b     = (const float*)d_in[19];
    const float* out_w    = (const float*)d_in[20];
    const float* out_b    = (const float*)d_in[21];
    const float* alpha    = (const float*)d_in[22];
    const float* lambd    = (const float*)d_in[23];
    const float* beta     = (const float*)d_in[24];

    float* pool;
    cudaGetSymbolAddress((void**)&pool, g_pool);
    float*  FR      = pool;
    float*  FN      = pool + 1 * TOT;
    float*  Fw      = pool + 2 * TOT;
    float*  cfr     = pool + 3 * TOT;
    float*  V       = pool + 5 * TOT;
    float*  qkvPre  = pool + 6 * TOT;
    float2* FQ      = (float2*)(pool + 9 * TOT);
    float2* FK      = (float2*)(pool + 11 * TOT);
    float*  S       = pool + 13 * TOT;
    float*  attnP   = pool + 14 * TOT;
    float*  w0      = pool + 15 * TOT;
    float*  w1      = w0 + 2048;
    float*  qkvb    = w1 + 2048;
    float*  m1      = qkvb + 1024;
    float*  m2      = m1 + 2048;

    __nv_bfloat16* bb = (__nv_bfloat16*)(pool + 15 * TOT + 16384);
    __nv_bfloat16* x1Th = bb;              __nv_bfloat16* x1Tl = bb + 1 * TOT;
    __nv_bfloat16* x2Th = bb + 2 * TOT;    __nv_bfloat16* x2Tl = x2Th + TOT / 2;
    __nv_bfloat16* FwTh = bb + 3 * TOT;    __nv_bfloat16* FwTl = bb + 4 * TOT;
    __nv_bfloat16* STh  = bb + 5 * TOT;    __nv_bfloat16* STl  = bb + 6 * TOT;
    __nv_bfloat16* fuTh = bb + 7 * TOT;    __nv_bfloat16* fuTl = bb + 8 * TOT;
    __nv_bfloat16* Qch  = bb + 9 * TOT;    __nv_bfloat16* Qcl  = bb + 10 * TOT;
    __nv_bfloat16* Krh  = bb + 11 * TOT;   __nv_bfloat16* Krl  = bb + 12 * TOT;
    __nv_bfloat16* small = bb + 13 * TOT;
    __nv_bfloat16* ach  = small;             __nv_bfloat16* acl  = ach + 524288;
    __nv_bfloat16* wrh  = acl + 524288;      __nv_bfloat16* wrl  = wrh + 65536;
    __nv_bfloat16* wnh  = wrl + 65536;       __nv_bfloat16* wnl  = wnh + 32768;
    __nv_bfloat16* wqh  = wnl + 32768;       __nv_bfloat16* wql  = wqh + 196608;
    __nv_bfloat16* owh  = wql + 196608;      __nv_bfloat16* owl  = owh + 65536;

    cudaFuncSetAttribute(mma_gemm, cudaFuncAttributeMaxDynamicSharedMemorySize, G_SMEM);
    cudaFuncSetAttribute(fft2_dw_kernel, cudaFuncAttributeMaxDynamicSharedMemorySize, DW_SMEM);
    cudaFuncSetAttribute(ifft2_prod_kernel, cudaFuncAttributeMaxDynamicSharedMemorySize, FFT_SMEM);

    cudaStream_t s1 = g_aux.s1, s2 = g_aux.s2;
    cudaEvent_t* ev = g_aux.ev;

    const int NIMG = BSZ * MID;
    const dim3 gN(16, 2, BSZ);
    const dim3 gT(128, 8, BSZ), bT(32, 8);
    const dim3 bT2(16, 16);

    // --- fork at capture origin
    cudaEventRecord(ev[8], 0);

    // --- s2: convW (off critical path) then means + MLP
    cudaStreamWaitEvent(s2, ev[8], 0);
    convW_kernel<<<1411, 256, 0, s2>>>(conv_r_w, conv_n_w, pq_w, pk_w, pv_w, out_w,
                                       pq_b, pk_b, pv_b,
                                       wrh, wrl, wnh, wnl, wqh, wql, owh, owl, qkvb);
    cudaEventRecord(ev[9], s2);           // weights ready
    meanX_kernel<<<BSZ * (C1 + C2), 256, 0, s2>>>(x1, x2, m1, m2);
    pooledmlp_kernel<<<BSZ, 256, 0, s2>>>(m1, m2, conv_r_w, conv_r_b, conv_n_w, conv_n_b,
                                          mlp_w1, mlp_w2, w0, w1);
    cudaEventRecord(ev[7], s2);

    // --- s1: x2 transpose + FN gemm
    cudaStreamWaitEvent(s1, ev[8], 0);
    convT_kernel<<<dim3(128, 4, BSZ), bT2, 0, s1>>>(x2, x2Th, x2Tl, C2, NPIX);
    cudaStreamWaitEvent(s1, ev[9], 0);
    mma_gemm<<<gN, 256, G_SMEM, s1>>>(wnh, wnl, 0, x2Th, x2Tl, (size_t)NPIX * C2,
                                      conv_n_b, FN, PB, 0, C2, C2, NPIX, 1.0f, 1);
    cudaEventRecord(ev[1], s1);

    // --- stream 0: x1 transpose + FR gemm
    convT_kernel<<<dim3(128, 8, BSZ), bT2>>>(x1, x1Th, x1Tl, C1, NPIX);
    cudaStreamWaitEvent(0, ev[9], 0);
    mma_gemm<<<gN, 256, G_SMEM>>>(wrh, wrl, 0, x1Th, x1Tl, (size_t)NPIX * C1,
                                  conv_r_b, FR, PB, 0, C1, C1, NPIX, 1.0f, 1);
    cudaStreamWaitEvent(0, ev[1], 0);
    cudaStreamWaitEvent(0, ev[7], 0);

    // --- blend
    blendT_kernel<<<gT, bT>>>(FR, FN, w0, w1, Fw, FwTh, FwTl);

    // --- merged QKV pre-convs
    mma_gemm<<<dim3(16, 6, BSZ), 256, G_SMEM>>>(wqh, wql, 0, FwTh, FwTl, (size_t)PB,
                                                qkvb, qkvPre, 3 * (size_t)PB, 0,
                                                MID, MID, NPIX, 1.0f, 1);
    cudaEventRecord(ev[2], 0);

    // --- s1: K chain; s2: V chain; 0: Q chain
    cudaStreamWaitEvent(s1, ev[2], 0);
    fft2_dw_kernel<<<NIMG, 256, DW_SMEM, s1>>>(qkvPre + PB, 3 * (size_t)PB, dk_w, dk_b,
                                               Krh, Krl, 1, FK);
    cudaEventRecord(ev[3], s1);
    cudaStreamWaitEvent(s2, ev[2], 0);
    dwconv3x3_kernel<<<NIMG, 256, 0, s2>>>(qkvPre + 2 * (size_t)PB, 3 * (size_t)PB,
                                           dv_w, dv_b, V);
    cudaEventRecord(ev[4], s2);
    fft2_dw_kernel<<<NIMG, 256, DW_SMEM>>>(qkvPre, 3 * (size_t)PB, dq_w, dq_b,
                                           Qch, Qcl, 0, FQ);
    cudaEventRecord(ev[5], 0);

    // --- s1: ifft2(FQ.*FK) + transpose (overlaps attn gemm on 0)
    cudaStreamWaitEvent(s1, ev[5], 0);
    ifft2_prod_kernel<<<NIMG, 256, FFT_SMEM, s1>>>(FQ, FK, S);
    convT_kernel<<<dim3(128, 8, BSZ), bT2, 0, s1>>>(S, STh, STl, MID, NPIX);
    cudaEventRecord(ev[6], s1);

    // --- 0: attn gemm (single wave) + softmax
    cudaStreamWaitEvent(0, ev[3], 0);
    mma_gemm<<<dim3(1, 2, BSZ * NSPLIT), 256, G_SMEM>>>(
        Qch, Qcl, (size_t)PB, Krh, Krl, (size_t)PB,
        nullptr, attnP, 65536, (size_t)BSZ * 65536,
        NPIX, NPIX / NSPLIT, MID, 4096.0f, NSPLIT);
    softmax_kernel<<<NIMG, 256>>>(attnP, ach, acl, alpha);

    // --- 0: cfr gemm
    cudaStreamWaitEvent(0, ev[6], 0);
    mma_gemm<<<gN, 256, G_SMEM>>>(ach, acl, (size_t)MID * MID, STh, STl, (size_t)PB,
                                  nullptr, cfr, PB, 0, MID, MID, NPIX, 1.0f, 1);

    // --- 0: fuse + final conv
    cudaStreamWaitEvent(0, ev[4], 0);
    fuseT_kernel<<<gT, bT>>>(Qch, Qcl, cfr, V, Fw, lambd, beta, fuTh, fuTl);
    mma_gemm<<<gN, 256, G_SMEM>>>(owh, owl, 0, fuTh, fuTl, (size_t)PB,
                                  out_b, (float*)d_out, PB, 0, MID, MID, NPIX, 1.0f, 1);
}

// round 14
// speedup vs baseline: 1.0327x; 1.0327x over previous
#include <cuda_runtime.h>
#include <cuda_bf16.h>
#include <math.h>
#include <stdint.h>

#define BSZ   8
#define C1    256
#define C2    128
#define MID   256
#define NPIX  4096
#define PB    (MID*NPIX)
#define TOT   ((size_t)BSZ*PB)
#define DD    32
#define NSPLIT 8
#define HROWS 33
#define HSZ   (HROWS * 64)

__device__ __forceinline__ uint32_t smem_u32(const void* p) {
    uint32_t a;
    asm("{ .reg .u64 t; cvta.to.shared.u64 t, %1; cvt.u32.u64 %0, t; }" : "=r"(a) : "l"(p));
    return a;
}

#define CP16(sa, ga) \
    asm volatile("cp.async.ca.shared.global [%0], [%1], 16;" :: "r"(sa), "l"(ga) : "memory")
#define CP_COMMIT() asm volatile("cp.async.commit_group;" ::: "memory")
#define CP_WAIT1()  asm volatile("cp.async.wait_group 1;" ::: "memory")

#define LDSM4(r0, r1, r2, r3, a) \
    asm volatile("ldmatrix.sync.aligned.m8n8.x4.shared.b16 {%0,%1,%2,%3}, [%4];" \
        : "=r"(r0), "=r"(r1), "=r"(r2), "=r"(r3) : "r"(a))

#define MMA16816(c, a, b0, b1) \
    asm volatile("mma.sync.aligned.m16n8k16.row.col.f32.bf16.bf16.f32 " \
        "{%0,%1,%2,%3}, {%4,%5,%6,%7}, {%8,%9}, {%0,%1,%2,%3};" \
        : "+f"((c)[0]), "+f"((c)[1]), "+f"((c)[2]), "+f"((c)[3]) \
        : "r"((a)[0]), "r"((a)[1]), "r"((a)[2]), "r"((a)[3]), "r"(b0), "r"(b1))

__device__ float g_pool[22ull * TOT];

struct Aux {
    cudaStream_t s1, s2;
    cudaEvent_t ev[10];
    Aux() {
        cudaStreamCreateWithFlags(&s1, cudaStreamNonBlocking);
        cudaStreamCreateWithFlags(&s2, cudaStreamNonBlocking);
        for (int i = 0; i < 10; ++i)
            cudaEventCreateWithFlags(&ev[i], cudaEventDisableTiming);
    }
};
static Aux g_aux;

// ---------------------------------------------------------------------------
// Split-bf16 tensor-core GEMM:  Y = scale*(A @ B^T) + bias
// ---------------------------------------------------------------------------
#define ST_BYTES 49152
#define G_SMEM   (3 * ST_BYTES)

__global__ __launch_bounds__(256, 1)
void mma_gemm(const __nv_bfloat16* __restrict__ Ah, const __nv_bfloat16* __restrict__ Al,
              size_t aStride,
              const __nv_bfloat16* __restrict__ Bh, const __nv_bfloat16* __restrict__ Bl,
              size_t bStride,
              const float* __restrict__ bias, float* __restrict__ Y,
              size_t yStride, size_t partStride,
              int Kstride, int Klen, int N, float scale, int NS)
{
    extern __shared__ __nv_bfloat16 dynsm[];
    const uint32_t smBase = smem_u32(dynsm);
    const int t = threadIdx.x, wid = t >> 5, lid = t & 31;
    const int wm = wid & 1, wn = wid >> 1;
    const int z = blockIdx.z;
    const int b = z / NS, s = z % NS;
    const int kBeg = s * Klen;
    const int m0 = blockIdx.y * 128, n0 = blockIdx.x * 256;

    const __nv_bfloat16* P[4];
    P[0] = Ah + (size_t)b * aStride + (size_t)m0 * Kstride + kBeg;
    P[1] = Al + (size_t)b * aStride + (size_t)m0 * Kstride + kBeg;
    P[2] = Bh + (size_t)b * bStride + (size_t)n0 * Kstride + kBeg;
    P[3] = Bl + (size_t)b * bStride + (size_t)n0 * Kstride + kBeg;
    float* Yp = Y + (size_t)b * yStride + (size_t)s * partStride;

    const int NC = Klen >> 5;

    int lrow[4], lc[4]; uint32_t lso[4];
#pragma unroll
    for (int r = 0; r < 4; ++r) {
        int q = t + 256 * r;
        lrow[r] = q >> 2; lc[r] = q & 3;
        lso[r] = lrow[r] * 64 + ((lc[r] ^ ((lrow[r] >> 1) & 3)) * 16);
    }

    const int lj = lid >> 3, lr = lid & 7;
    uint32_t aAddr[4], bAddr[4];
#pragma unroll
    for (int i = 0; i < 4; ++i) {
        int row = wm * 64 + i * 16 + ((lj & 1) << 3) + lr;
        int c = (lj >> 1) ^ ((row >> 1) & 3);
        aAddr[i] = smBase + row * 64 + c * 16;
    }
#pragma unroll
    for (int p = 0; p < 4; ++p) {
        int n = wn * 64 + p * 16 + ((lj >> 1) << 3) + lr;
        int c = (lj & 1) ^ ((n >> 1) & 3);
        bAddr[p] = smBase + 16384 + n * 64 + c * 16;
    }

    float acc[4][8][4];
#pragma unroll
    for (int i = 0; i < 4; ++i)
#pragma unroll
        for (int j = 0; j < 8; ++j)
#pragma unroll
            for (int e = 0; e < 4; ++e) acc[i][j][e] = 0.f;

#define LOADSTAGE(CH, SLOT) do {                                              \
        int kc_ = (CH) << 5;                                                  \
        uint32_t so_ = (uint32_t)(SLOT) * ST_BYTES;                           \
        _Pragma("unroll")                                                     \
        for (int pl_ = 0; pl_ < 2; ++pl_) {                                   \
            const __nv_bfloat16* src_ = P[pl_] + kc_;                         \
            uint32_t dst_ = smBase + so_ + pl_ * 8192;                        \
            _Pragma("unroll")                                                 \
            for (int r_ = 0; r_ < 2; ++r_)                                    \
                CP16(dst_ + lso[r_], src_ + (size_t)lrow[r_] * Kstride + lc[r_] * 8); \
        }                                                                     \
        _Pragma("unroll")                                                     \
        for (int pl_ = 2; pl_ < 4; ++pl_) {                                   \
            const __nv_bfloat16* src_ = P[pl_] + kc_;                         \
            uint32_t dst_ = smBase + so_ + 16384 + (pl_ - 2) * 16384;         \
            _Pragma("unroll")                                                 \
            for (int r_ = 0; r_ < 4; ++r_)                                    \
                CP16(dst_ + lso[r_], src_ + (size_t)lrow[r_] * Kstride + lc[r_] * 8); \
        }                                                                     \
    } while (0)

    LOADSTAGE(0, 0); CP_COMMIT();
    LOADSTAGE(1, 1); CP_COMMIT();

    for (int ch = 0; ch < NC; ++ch) {
        CP_WAIT1();
        __syncthreads();
        int nxt = ch + 2;
        if (nxt < NC) LOADSTAGE(nxt, nxt % 3);
        CP_COMMIT();

        const uint32_t stoff = (uint32_t)(ch % 3) * ST_BYTES;
#pragma unroll
        for (int kt = 0; kt < 2; ++kt) {
            const uint32_t kx = kt ? 32u : 0u;
            uint32_t aH[4][4], bH[4][4], aL[4][4], bL[4][4];
#pragma unroll
            for (int i = 0; i < 4; ++i)
                LDSM4(aH[i][0], aH[i][1], aH[i][2], aH[i][3], (aAddr[i] + stoff) ^ kx);
#pragma unroll
            for (int p = 0; p < 4; ++p)
                LDSM4(bH[p][0], bH[p][1], bH[p][2], bH[p][3], (bAddr[p] + stoff) ^ kx);
#pragma unroll
            for (int i = 0; i < 4; ++i)
                LDSM4(aL[i][0], aL[i][1], aL[i][2], aL[i][3], (aAddr[i] + stoff + 8192) ^ kx);
#pragma unroll
            for (int p = 0; p < 4; ++p)
                LDSM4(bL[p][0], bL[p][1], bL[p][2], bL[p][3], (bAddr[p] + stoff + 16384) ^ kx);
#pragma unroll
            for (int i = 0; i < 4; ++i)
#pragma unroll
                for (int j = 0; j < 8; ++j)
                    MMA16816(acc[i][j], aH[i], bH[j >> 1][(j & 1) * 2], bH[j >> 1][(j & 1) * 2 + 1]);
#pragma unroll
            for (int i = 0; i < 4; ++i)
#pragma unroll
                for (int j = 0; j < 8; ++j)
                    MMA16816(acc[i][j], aL[i], bH[j >> 1][(j & 1) * 2], bH[j >> 1][(j & 1) * 2 + 1]);
#pragma unroll
            for (int i = 0; i < 4; ++i)
#pragma unroll
                for (int j = 0; j < 8; ++j)
                    MMA16816(acc[i][j], aH[i], bL[j >> 1][(j & 1) * 2], bL[j >> 1][(j & 1) * 2 + 1]);
        }
    }
#undef LOADSTAGE

    const int groupID = lid >> 2, tid4 = lid & 3;
#pragma unroll
    for (int i = 0; i < 4; ++i) {
        int r0 = m0 + wm * 64 + i * 16 + groupID;
        int r1 = r0 + 8;
        float bv0 = bias ? bias[r0] : 0.f;
        float bv1 = bias ? bias[r1] : 0.f;
        float* y0 = Yp + (size_t)r0 * N + n0 + wn * 64 + tid4 * 2;
        float* y1 = Yp + (size_t)r1 * N + n0 + wn * 64 + tid4 * 2;
#pragma unroll
        for (int j = 0; j < 8; ++j) {
            *(float2*)(y0 + j * 8) = make_float2(fmaf(acc[i][j][0], scale, bv0),
                                                 fmaf(acc[i][j][1], scale, bv0));
            *(float2*)(y1 + j * 8) = make_float2(fmaf(acc[i][j][2], scale, bv1),
                                                 fmaf(acc[i][j][3], scale, bv1));
        }
    }
}

// ---------------------------------------------------------------------------
// Radix-8x8 FFT machinery
// ---------------------------------------------------------------------------
__device__ __forceinline__ float2 cmulf(float2 a, float2 b) {
    return make_float2(a.x * b.x - a.y * b.y, a.x * b.y + a.y * b.x);
}

template<int S>
__device__ __forceinline__ void fft8(float2 v[8])
{
    const float C0 = 0.70710678118654752f;
    const float SG = (float)S;
    float2 a0 = make_float2(v[0].x + v[4].x, v[0].y + v[4].y);
    float2 a1 = make_float2(v[1].x + v[5].x, v[1].y + v[5].y);
    float2 a2 = make_float2(v[2].x + v[6].x, v[2].y + v[6].y);
    float2 a3 = make_float2(v[3].x + v[7].x, v[3].y + v[7].y);
    float2 b0 = make_float2(v[0].x - v[4].x, v[0].y - v[4].y);
    float2 b1 = make_float2(v[1].x - v[5].x, v[1].y - v[5].y);
    float2 b2 = make_float2(v[2].x - v[6].x, v[2].y - v[6].y);
    float2 b3 = make_float2(v[3].x - v[7].x, v[3].y - v[7].y);
    float2 t1 = make_float2(C0 * (b1.x - SG * b1.y), C0 * (SG * b1.x + b1.y));
    float2 t2 = make_float2(-SG * b2.y, SG * b2.x);
    float2 t3 = make_float2(C0 * (-b3.x - SG * b3.y), C0 * (SG * b3.x - b3.y));
    float2 c0 = make_float2(a0.x + a2.x, a0.y + a2.y);
    float2 c1 = make_float2(a1.x + a3.x, a1.y + a3.y);
    float2 d0 = make_float2(a0.x - a2.x, a0.y - a2.y);
    float2 e0 = make_float2(a1.x - a3.x, a1.y - a3.y);
    float2 d1 = make_float2(-SG * e0.y, SG * e0.x);
    float2 c2 = make_float2(b0.x + t2.x, b0.y + t2.y);
    float2 c3 = make_float2(t1.x + t3.x, t1.y + t3.y);
    float2 d2 = make_float2(b0.x - t2.x, b0.y - t2.y);
    float2 e1 = make_float2(t1.x - t3.x, t1.y - t3.y);
    float2 d3 = make_float2(-SG * e1.y, SG * e1.x);
    v[0] = make_float2(c0.x + c1.x, c0.y + c1.y);
    v[1] = make_float2(c2.x + c3.x, c2.y + c3.y);
    v[2] = make_float2(d0.x + d1.x, d0.y + d1.y);
    v[3] = make_float2(d2.x + d3.x, d2.y + d3.y);
    v[4] = make_float2(c0.x - c1.x, c0.y - c1.y);
    v[5] = make_float2(c2.x - c3.x, c2.y - c3.y);
    v[6] = make_float2(d0.x - d1.x, d0.y - d1.y);
    v[7] = make_float2(d2.x - d3.x, d2.y - d3.y);
}

template<int S>
__device__ __forceinline__ void fftpass(float2* bin, float2* bout, const float2* tw, int t)
{
    const int r = t >> 2, q = t & 3;
    const int rb = r * 65;
    float2 g[2][8];
#pragma unroll
    for (int gi = 0; gi < 2; ++gi) {
        int bcol = q + 4 * gi;
#pragma unroll
        for (int a = 0; a < 8; ++a) g[gi][a] = bin[rb + 8 * a + bcol];
        fft8<S>(g[gi]);
#pragma unroll
        for (int k1 = 0; k1 < 8; ++k1) g[gi][k1] = cmulf(g[gi][k1], tw[bcol * 8 + k1]);
    }
#pragma unroll
    for (int gi = 0; gi < 2; ++gi) {
        int bcol = q + 4 * gi;
#pragma unroll
        for (int k1 = 0; k1 < 8; ++k1) bin[rb + k1 * 8 + bcol] = g[gi][k1];
    }
    __syncwarp();
#pragma unroll
    for (int gi = 0; gi < 2; ++gi) {
        int k1 = q + 4 * gi;
        float2 h[8];
#pragma unroll
        for (int bcol = 0; bcol < 8; ++bcol) h[bcol] = bin[rb + k1 * 8 + bcol];
        fft8<S>(h);
#pragma unroll
        for (int k2 = 0; k2 < 8; ++k2) bout[(k1 + 8 * k2) * 65 + r] = h[k2];
    }
}

#define FFT_SMEM ((2 * 64 * 65 + 64) * 8)
#define DW_SMEM  (FFT_SMEM + 64 * 65 * 4)

__global__ void fft2_dw_kernel(const float* __restrict__ pre, size_t preStride,
                               const float* __restrict__ wt, const float* __restrict__ bs,
                               __nv_bfloat16* __restrict__ oh, __nv_bfloat16* __restrict__ ol,
                               int rev, float2* __restrict__ Xout)
{
    extern __shared__ float2 fsm[];
    float2* bufA = fsm;
    float2* bufB = fsm + 64 * 65;
    float2* tw   = fsm + 2 * 64 * 65;
    float*  xin  = (float*)(fsm + 2 * 64 * 65 + 64);
    int t = threadIdx.x;
    int img = blockIdx.x;
    int c = img & 255;
    if (t < 64) {
        int bcol = t >> 3, k1 = t & 7;
        float sn, cs; sincospif(-(float)(bcol * k1) / 32.0f, &sn, &cs);
        tw[t] = make_float2(cs, sn);
    }
    const float* xi = pre + (size_t)(img >> 8) * preStride + ((size_t)c << 12);
    for (int i = t; i < 4096; i += 256) xin[(i >> 6) * 65 + (i & 63)] = xi[i];
    const float* wp = wt + c * 9;
    float k0 = wp[0], k1 = wp[1], k2 = wp[2], k3 = wp[3], k4 = wp[4],
          k5 = wp[5], k6 = wp[6], k7 = wp[7], k8 = wp[8];
    float bv = bs[c];
    __syncthreads();
    for (int i = t; i < 4096; i += 256) {
        int h = i >> 6, w = i & 63;
        const float* row = xin + h * 65;
        float s = bv + k4 * row[w];
        bool ht = h > 0, hb = h < 63, wl = w > 0, wr = w < 63;
        if (ht) {
            const float* ru = row - 65;
            s += k1 * ru[w];
            if (wl) s += k0 * ru[w - 1];
            if (wr) s += k2 * ru[w + 1];
        }
        if (wl) s += k3 * row[w - 1];
        if (wr) s += k5 * row[w + 1];
        if (hb) {
            const float* rd = row + 65;
            s += k7 * rd[w];
            if (wl) s += k6 * rd[w - 1];
            if (wr) s += k8 * rd[w + 1];
        }
        bufA[h * 65 + w] = make_float2(s, 0.f);
        if (oh) {
            size_t base = (size_t)img << 12;
            int oi = rev ? ((((64 - h) & 63) << 6) | ((64 - w) & 63)) : i;
            __nv_bfloat16 hh = __float2bfloat16(s);
            oh[base + oi] = hh;
            ol[base + oi] = __float2bfloat16(s - __bfloat162float(hh));
        }
    }
    __syncthreads();
    fftpass<-1>(bufA, bufB, tw, t);
    __syncthreads();
    fftpass<-1>(bufB, bufA, tw, t);
    __syncthreads();
    float2* o = Xout + (size_t)blockIdx.x * HSZ;
    for (int i = t; i < HSZ; i += 256)
        o[i] = bufA[(i >> 6) * 65 + (i & 63)];
}

__global__ void ifft2_prod_kernel(const float2* __restrict__ FQ, const float2* __restrict__ FK,
                                  float* __restrict__ out)
{
    extern __shared__ float2 fsm[];
    float2* bufA = fsm;
    float2* bufB = fsm + 64 * 65;
    float2* tw   = fsm + 2 * 64 * 65;
    int t = threadIdx.x;
    if (t < 64) {
        int bcol = t >> 3, k1 = t & 7;
        float sn, cs; sincospif((float)(bcol * k1) / 32.0f, &sn, &cs);
        tw[t] = make_float2(cs, sn);
    }
    const float2* q = FQ + (size_t)blockIdx.x * HSZ;
    const float2* kk = FK + (size_t)blockIdx.x * HSZ;
    for (int i = t; i < HSZ; i += 256) {
        float2 a = q[i], b = kk[i];
        bufA[(i >> 6) * 65 + (i & 63)] =
            make_float2(a.x * b.x - a.y * b.y, a.x * b.y + a.y * b.x);
    }
    __syncthreads();
    for (int i = t; i < 31 * 64; i += 256) {
        int u = 33 + (i >> 6), v = i & 63;
        float2 m = bufA[(64 - u) * 65 + ((64 - v) & 63)];
        bufA[u * 65 + v] = make_float2(m.x, -m.y);
    }
    __syncthreads();
    fftpass<1>(bufA, bufB, tw, t);
    __syncthreads();
    fftpass<1>(bufB, bufA, tw, t);
    __syncthreads();
    float* o = out + (size_t)blockIdx.x * 4096;
    for (int i = t; i < 4096; i += 256)
        o[i] = bufA[(i >> 6) * 65 + (i & 63)].x * (1.0f / 4096.0f);
}

// ---------------------------------------------------------------------------
__global__ void convW_kernel(
    const float* __restrict__ wr, const float* __restrict__ wn,
    const float* __restrict__ pq, const float* __restrict__ pk, const float* __restrict__ pv,
    const float* __restrict__ ow,
    const float* __restrict__ pqb, const float* __restrict__ pkb, const float* __restrict__ pvb,
    __nv_bfloat16* wrh, __nv_bfloat16* wrl, __nv_bfloat16* wnh, __nv_bfloat16* wnl,
    __nv_bfloat16* wqh, __nv_bfloat16* wql, __nv_bfloat16* owh, __nv_bfloat16* owl,
    float* qkvb)
{
    int i = blockIdx.x * 256 + threadIdx.x;
    if (i < 65536) {
        float x = wr[i]; __nv_bfloat16 h = __float2bfloat16(x);
        wrh[i] = h; wrl[i] = __float2bfloat16(x - __bfloat162float(h));
    } else if (i < 98304) {
        int j = i - 65536;
        float x = wn[j]; __nv_bfloat16 h = __float2bfloat16(x);
        wnh[j] = h; wnl[j] = __float2bfloat16(x - __bfloat162float(h));
    } else if (i < 294912) {
        int j = i - 98304;
        const float* s3 = (j < 65536) ? pq : (j < 131072) ? pk : pv;
        float x = s3[j & 65535]; __nv_bfloat16 h = __float2bfloat16(x);
        wqh[j] = h; wql[j] = __float2bfloat16(x - __bfloat162float(h));
    } else if (i < 360448) {
        int j = i - 294912;
        float x = ow[j]; __nv_bfloat16 h = __float2bfloat16(x);
        owh[j] = h; owl[j] = __float2bfloat16(x - __bfloat162float(h));
    } else if (i < 361216) {
        int j = i - 360448;
        qkvb[j] = (j < 256) ? pqb[j] : (j < 512) ? pkb[j - 256] : pvb[j - 512];
    }
}

// packed-store transpose: fp32 [R][C] -> split-bf16 [C][R], 2 bf16 per STG.32
__global__ void convT_kernel(const float* __restrict__ in,
                             __nv_bfloat16* __restrict__ oh, __nv_bfloat16* __restrict__ ol,
                             int R, int C)
{
    __shared__ float tile[32][33];
    int b = blockIdx.z;
    const float* ip = in + (size_t)b * R * C;
    uint32_t* ohp = (uint32_t*)(oh + (size_t)b * R * C);
    uint32_t* olp = (uint32_t*)(ol + (size_t)b * R * C);
    int c0 = blockIdx.x * 32, r0 = blockIdx.y * 32;
    int tx = threadIdx.x, ty = threadIdx.y;   // (16,16)
#pragma unroll
    for (int j = 0; j < 2; ++j) {
        int row = ty + 16 * j;
        float2 v = *(const float2*)&ip[(size_t)(r0 + row) * C + c0 + 2 * tx];
        tile[row][2 * tx]     = v.x;
        tile[row][2 * tx + 1] = v.y;
    }
    __syncthreads();
#pragma unroll
    for (int j = 0; j < 2; ++j) {
        int cc = ty + 16 * j;
        float a = tile[2 * tx][cc], bv = tile[2 * tx + 1][cc];
        __nv_bfloat16 ha = __float2bfloat16(a), hb = __float2bfloat16(bv);
        __nv_bfloat16 la = __float2bfloat16(a - __bfloat162float(ha));
        __nv_bfloat16 lb = __float2bfloat16(bv - __bfloat162float(hb));
        size_t o = ((size_t)(c0 + cc) * R + r0 + 2 * tx) >> 1;
        ohp[o] = ((uint32_t)__bfloat16_as_ushort(hb) << 16) | __bfloat16_as_ushort(ha);
        olp[o] = ((uint32_t)__bfloat16_as_ushort(lb) << 16) | __bfloat16_as_ushort(la);
    }
}

// ---------------------------------------------------------------------------
__global__ void meanX_kernel(const float* __restrict__ x1, const float* __restrict__ x2,
                             float* __restrict__ m1, float* __restrict__ m2)
{
    __shared__ float red[256];
    int img = blockIdx.x, t = threadIdx.x;
    const float* src; float* dst; int idx;
    if (img < BSZ * C1) { src = x1 + (size_t)img * NPIX; dst = m1; idx = img; }
    else { idx = img - BSZ * C1; src = x2 + (size_t)idx * NPIX; dst = m2; }
    float s = 0.f;
    for (int i = t; i < NPIX; i += 256) s += src[i];
    red[t] = s; __syncthreads();
    for (int st = 128; st > 0; st >>= 1) {
        if (t < st) red[t] += red[t + st];
        __syncthreads();
    }
    if (t == 0) dst[idx] = red[0] * (1.0f / NPIX);
}

__global__ void pooledmlp_kernel(const float* __restrict__ m1, const float* __restrict__ m2,
                                 const float* __restrict__ wr, const float* __restrict__ br,
                                 const float* __restrict__ wn, const float* __restrict__ bn,
                                 const float* __restrict__ w1, const float* __restrict__ w2,
                                 float* __restrict__ a0out, float* __restrict__ a1out)
{
    __shared__ float pooled[MID];
    __shared__ float hs[DD];
    int b = blockIdx.x, t = threadIdx.x;
    {
        int c = t;
        float s = br[c] + bn[c];
        const float* wrow = wr + c * C1;
        const float* m1b = m1 + b * C1;
#pragma unroll 8
        for (int i = 0; i < C1; ++i) s += wrow[i] * m1b[i];
        const float* nrow = wn + c * C2;
        const float* m2b = m2 + b * C2;
#pragma unroll 8
        for (int j = 0; j < C2; ++j) s += nrow[j] * m2b[j];
        pooled[c] = s;
    }
    __syncthreads();
    {
        int d = t >> 3, ln = t & 7;
        float s = 0.f;
        for (int c = ln; c < MID; c += 8) s += pooled[c] * w1[d * MID + c];
#pragma unroll
        for (int k = 4; k > 0; k >>= 1) s += __shfl_down_sync(0xffffffffu, s, k, 8);
        if (ln == 0) hs[d] = fmaxf(s, 0.f);
    }
    __syncthreads();
    {
        int c = t;
        float a0 = 0.f, a1 = 0.f;
#pragma unroll
        for (int d = 0; d < DD; ++d) {
            float hv = hs[d];
            a0 += hv * w2[c * DD + d];
            a1 += hv * w2[(MID + c) * DD + d];
        }
        float m = fmaxf(a0, a1);
        float e0 = expf(a0 - m), e1 = expf(a1 - m);
        float inv = 1.0f / (e0 + e1);
        a0out[b * MID + c] = e0 * inv;
        a1out[b * MID + c] = e1 * inv;
    }
}

__global__ void blendT_kernel(const float* __restrict__ FR, const float* __restrict__ FN,
                              const float* __restrict__ w0, const float* __restrict__ w1,
                              float* __restrict__ Fw,
                              __nv_bfloat16* __restrict__ oh, __nv_bfloat16* __restrict__ ol)
{
    __shared__ float tile[32][33];
    int b = blockIdx.z;
    int p0 = blockIdx.x * 32, c0 = blockIdx.y * 32;
    int tx = threadIdx.x, ty = threadIdx.y;
#pragma unroll
    for (int j = 0; j < 4; ++j) {
        int c = c0 + ty + 8 * j;
        size_t idx = (size_t)b * PB + (size_t)c * NPIX + p0 + tx;
        float v = w0[b * MID + c] * FR[idx] + w1[b * MID + c] * FN[idx];
        Fw[idx] = v;
        tile[ty + 8 * j][tx] = v;
    }
    __syncthreads();
#pragma unroll
    for (int j = 0; j < 4; ++j) {
        float x = tile[tx][ty + 8 * j];
        __nv_bfloat16 h = __float2bfloat16(x);
        size_t o = (size_t)b * PB + (size_t)(p0 + ty + 8 * j) * MID + c0 + tx;
        oh[o] = h;
        ol[o] = __float2bfloat16(x - __bfloat162float(h));
    }
}

__global__ void dwconv3x3_kernel(const float* __restrict__ x, size_t preStride,
                                 const float* __restrict__ wt,
                                 const float* __restrict__ bs, float* __restrict__ y)
{
    __shared__ float xs[64][65];
    int img = blockIdx.x;
    int c = img & 255;
    const float* xi = x + (size_t)(img >> 8) * preStride + ((size_t)c << 12);
    for (int i = threadIdx.x; i < NPIX; i += 256) xs[i >> 6][i & 63] = xi[i];
    const float* wp = wt + c * 9;
    float k0 = wp[0], k1 = wp[1], k2 = wp[2], k3 = wp[3], k4 = wp[4],
          k5 = wp[5], k6 = wp[6], k7 = wp[7], k8 = wp[8];
    float bv = bs[c];
    __syncthreads();
    for (int i = threadIdx.x; i < NPIX; i += 256) {
        int h = i >> 6, w = i & 63;
        float s = bv + k4 * xs[h][w];
        bool ht = h > 0, hb = h < 63, wl = w > 0, wr = w < 63;
        if (ht) {
            s += k1 * xs[h - 1][w];
            if (wl) s += k0 * xs[h - 1][w - 1];
            if (wr) s += k2 * xs[h - 1][w + 1];
        }
        if (wl) s += k3 * xs[h][w - 1];
        if (wr) s += k5 * xs[h][w + 1];
        if (hb) {
            s += k7 * xs[h + 1][w];
            if (wl) s += k6 * xs[h + 1][w - 1];
            if (wr) s += k8 * xs[h + 1][w + 1];
        }
        y[((size_t)img << 12) + i] = s;
    }
}

__global__ void softmax_kernel(const float* __restrict__ attnP,
                               __nv_bfloat16* __restrict__ ah, __nv_bfloat16* __restrict__ al,
                               const float* __restrict__ alpha)
{
    __shared__ float red[256];
    int row = blockIdx.x, t = threadIdx.x;
    float v = 0.f;
#pragma unroll
    for (int s = 0; s < NSPLIT; ++s)
        v += attnP[(size_t)s * (BSZ * 65536) + (size_t)row * 256 + t];
    float inva = 1.0f / (*alpha);
    v = fabsf(v) * inva;
    red[t] = v; __syncthreads();
    for (int s = 128; s > 0; s >>= 1) {
        if (t < s) red[t] = fmaxf(red[t], red[t + s]);
        __syncthreads();
    }
    float m = red[0]; __syncthreads();
    float e = expf(v - m);
    red[t] = e; __syncthreads();
    for (int s = 128; s > 0; s >>= 1) {
        if (t < s) red[t] += red[t + s];
        __syncthreads();
    }
    float val = e / red[0];
    __nv_bfloat16 h = __float2bfloat16(val);
    ah[(size_t)row * 256 + t] = h;
    al[(size_t)row * 256 + t] = __float2bfloat16(val - __bfloat162float(h));
}

__global__ void fuseT_kernel(const __nv_bfloat16* __restrict__ Qh,
                             const __nv_bfloat16* __restrict__ Ql,
                             const float* __restrict__ cfr,
                             const float* __restrict__ V, const float* __restrict__ Fw,
                             const float* __restrict__ lambd, const float* __restrict__ beta,
                             __nv_bfloat16* __restrict__ oh, __nv_bfloat16* __restrict__ ol)
{
    __shared__ float tile[32][33];
    int b = blockIdx.z;
    int p0 = blockIdx.x * 32, c0 = blockIdx.y * 32;
    int tx = threadIdx.x, ty = threadIdx.y;
    float l = *lambd, be = *beta;
#pragma unroll
    for (int j = 0; j < 4; ++j) {
        size_t idx = (size_t)b * PB + (size_t)(c0 + ty + 8 * j) * NPIX + p0 + tx;
        float q = __bfloat162float(Qh[idx]) + __bfloat162float(Ql[idx]);
        float c = cfr[idx], v = V[idx], f = Fw[idx];
        float freq_out = q * c + v - l * v * c;
        tile[ty + 8 * j][tx] = be * freq_out + (1.0f - be) * f;
    }
    __syncthreads();
#pragma unroll
    for (int j = 0; j < 4; ++j) {
        float x = tile[tx][ty + 8 * j];
        __nv_bfloat16 h = __float2bfloat16(x);
        size_t o = (size_t)b * PB + (size_t)(p0 + ty + 8 * j) * MID + c0 + tx;
        oh[o] = h;
        ol[o] = __float2bfloat16(x - __bfloat162float(h));
    }
}

// ---------------------------------------------------------------------------
extern "C" void kernel_launch(void* const* d_in, const int* in_sizes, int n_in,
                              void* d_out, int out_size)
{
    const float* x1       = (const float*)d_in[0];
    const float* x2       = (const float*)d_in[1];
    const float* conv_r_w = (const float*)d_in[2];
    const float* conv_r_b = (const float*)d_in[3];
    const float* conv_n_w = (const float*)d_in[4];
    const float* conv_n_b = (const float*)d_in[5];
    const float* mlp_w1   = (const float*)d_in[6];
    const float* mlp_w2   = (const float*)d_in[7];
    const float* pq_w     = (const float*)d_in[8];
    const float* pq_b     = (const float*)d_in[9];
    const float* dq_w     = (const float*)d_in[10];
    const float* dq_b     = (const float*)d_in[11];
    const float* pk_w     = (const float*)d_in[12];
    const float* pk_b     = (const float*)d_in[13];
    const float* dk_w     = (const float*)d_in[14];
    const float* dk_b     = (const float*)d_in[15];
    const float* pv_w     = (const float*)d_in[16];
    const float* pv_b     = (const float*)d_in[17];
    const float* dv_w     = (const float*)d_in[18];
    const float* dv_b     = (const float*)d_in[19];
    const float* out_w    = (const float*)d_in[20];
    const float* out_b    = (const float*)d_in[21];
    const float* alpha    = (const float*)d_in[22];
    const float* lambd    = (const float*)d_in[23];
    const float* beta     = (const float*)d_in[24];

    float* pool;
    cudaGetSymbolAddress((void**)&pool, g_pool);
    float*  FR      = pool;
    float*  FN      = pool + 1 * TOT;
    float*  Fw      = pool + 2 * TOT;
    float*  cfr     = pool + 3 * TOT;
    float*  V       = pool + 5 * TOT;
    float*  qkvPre  = pool + 6 * TOT;
    float2* FQ      = (float2*)(pool + 9 * TOT);
    float2* FK      = (float2*)(pool + 11 * TOT);
    float*  S       = pool + 13 * TOT;
    float*  attnP   = pool + 14 * TOT;
    float*  w0      = pool + 15 * TOT;
    float*  w1      = w0 + 2048;
    float*  qkvb    = w1 + 2048;
    float*  m1      = qkvb + 1024;
    float*  m2      = m1 + 2048;

    __nv_bfloat16* bb = (__nv_bfloat16*)(pool + 15 * TOT + 16384);
    __nv_bfloat16* x1Th = bb;              __nv_bfloat16* x1Tl = bb + 1 * TOT;
    __nv_bfloat16* x2Th = bb + 2 * TOT;    __nv_bfloat16* x2Tl = x2Th + TOT / 2;
    __nv_bfloat16* FwTh = bb + 3 * TOT;    __nv_bfloat16* FwTl = bb + 4 * TOT;
    __nv_bfloat16* STh  = bb + 5 * TOT;    __nv_bfloat16* STl  = bb + 6 * TOT;
    __nv_bfloat16* fuTh = bb + 7 * TOT;    __nv_bfloat16* fuTl = bb + 8 * TOT;
    __nv_bfloat16* Qch  = bb + 9 * TOT;    __nv_bfloat16* Qcl  = bb + 10 * TOT;
    __nv_bfloat16* Krh  = bb + 11 * TOT;   __nv_bfloat16* Krl  = bb + 12 * TOT;
    __nv_bfloat16* small = bb + 13 * TOT;
    __nv_bfloat16* ach  = small;             __nv_bfloat16* acl  = ach + 524288;
    __nv_bfloat16* wrh  = acl + 524288;      __nv_bfloat16* wrl  = wrh + 65536;
    __nv_bfloat16* wnh  = wrl + 65536;       __nv_bfloat16* wnl  = wnh + 32768;
    __nv_bfloat16* wqh  = wnl + 32768;       __nv_bfloat16* wql  = wqh + 196608;
    __nv_bfloat16* owh  = wql + 196608;      __nv_bfloat16* owl  = owh + 65536;

    cudaFuncSetAttribute(mma_gemm, cudaFuncAttributeMaxDynamicSharedMemorySize, G_SMEM);
    cudaFuncSetAttribute(fft2_dw_kernel, cudaFuncAttributeMaxDynamicSharedMemorySize, DW_SMEM);
    cudaFuncSetAttribute(ifft2_prod_kernel, cudaFuncAttributeMaxDynamicSharedMemorySize, FFT_SMEM);

    cudaStream_t s1 = g_aux.s1, s2 = g_aux.s2;
    cudaEvent_t* ev = g_aux.ev;

    const int NIMG = BSZ * MID;
    const dim3 gN(16, 2, BSZ);
    const dim3 gT(128, 8, BSZ), bT(32, 8);
    const dim3 bT2(16, 16);

    // --- fork event at capture origin (R11 schedule)
    cudaEventRecord(ev[8], 0);

    // --- s2: channel-attention weights from input means
    cudaStreamWaitEvent(s2, ev[8], 0);
    meanX_kernel<<<BSZ * (C1 + C2), 256, 0, s2>>>(x1, x2, m1, m2);
    pooledmlp_kernel<<<BSZ, 256, 0, s2>>>(m1, m2, conv_r_w, conv_r_b, conv_n_w, conv_n_b,
                                          mlp_w1, mlp_w2, w0, w1);
    cudaEventRecord(ev[7], s2);

    // --- stream 0: weights
    convW_kernel<<<1411, 256>>>(conv_r_w, conv_n_w, pq_w, pk_w, pv_w, out_w,
                                pq_b, pk_b, pv_b,
                                wrh, wrl, wnh, wnl, wqh, wql, owh, owl, qkvb);
    cudaEventRecord(ev[0], 0);

    // --- s1: x2 chain
    cudaStreamWaitEvent(s1, ev[0], 0);
    convT_kernel<<<dim3(128, 4, BSZ), bT2, 0, s1>>>(x2, x2Th, x2Tl, C2, NPIX);
    mma_gemm<<<gN, 256, G_SMEM, s1>>>(wnh, wnl, 0, x2Th, x2Tl, (size_t)NPIX * C2,
                                      conv_n_b, FN, PB, 0, C2, C2, NPIX, 1.0f, 1);
    cudaEventRecord(ev[1], s1);

    // --- stream 0: x1 chain
    convT_kernel<<<dim3(128, 8, BSZ), bT2>>>(x1, x1Th, x1Tl, C1, NPIX);
    mma_gemm<<<gN, 256, G_SMEM>>>(wrh, wrl, 0, x1Th, x1Tl, (size_t)NPIX * C1,
                                  conv_r_b, FR, PB, 0, C1, C1, NPIX, 1.0f, 1);
    cudaStreamWaitEvent(0, ev[1], 0);
    cudaStreamWaitEvent(0, ev[7], 0);

    // --- blend
    blendT_kernel<<<gT, bT>>>(FR, FN, w0, w1, Fw, FwTh, FwTl);

    // --- merged QKV pre-convs
    mma_gemm<<<dim3(16, 6, BSZ), 256, G_SMEM>>>(wqh, wql, 0, FwTh, FwTl, (size_t)PB,
                                                qkvb, qkvPre, 3 * (size_t)PB, 0,
                                                MID, MID, NPIX, 1.0f, 1);
    cudaEventRecord(ev[2], 0);

    // --- s1: K chain; s2: V chain; 0: Q chain
    cudaStreamWaitEvent(s1, ev[2], 0);
    fft2_dw_kernel<<<NIMG, 256, DW_SMEM, s1>>>(qkvPre + PB, 3 * (size_t)PB, dk_w, dk_b,
                                               Krh, Krl, 1, FK);
    cudaEventRecord(ev[3], s1);
    cudaStreamWaitEvent(s2, ev[2], 0);
    dwconv3x3_kernel<<<NIMG, 256, 0, s2>>>(qkvPre + 2 * (size_t)PB, 3 * (size_t)PB,
                                           dv_w, dv_b, V);
    cudaEventRecord(ev[4], s2);
    fft2_dw_kernel<<<NIMG, 256, DW_SMEM>>>(qkvPre, 3 * (size_t)PB, dq_w, dq_b,
                                           Qch, Qcl, 0, FQ);
    cudaEventRecord(ev[5], 0);

    // --- s1: ifft2(FQ.*FK) + transpose (overlaps attn gemm on 0)
    cudaStreamWaitEvent(s1, ev[5], 0);
    ifft2_prod_kernel<<<NIMG, 256, FFT_SMEM, s1>>>(FQ, FK, S);
    convT_kernel<<<dim3(128, 8, BSZ), bT2, 0, s1>>>(S, STh, STl, MID, NPIX);
    cudaEventRecord(ev[6], s1);

    // --- 0: attn gemm (single wave) + softmax
    cudaStreamWaitEvent(0, ev[3], 0);
    mma_gemm<<<dim3(1, 2, BSZ * NSPLIT), 256, G_SMEM>>>(
        Qch, Qcl, (size_t)PB, Krh, Krl, (size_t)PB,
        nullptr, attnP, 65536, (size_t)BSZ * 65536,
        NPIX, NPIX / NSPLIT, MID, 4096.0f, NSPLIT);
    softmax_kernel<<<NIMG, 256>>>(attnP, ach, acl, alpha);

    // --- 0: cfr gemm
    cudaStreamWaitEvent(0, ev[6], 0);
    mma_gemm<<<gN, 256, G_SMEM>>>(ach, acl, (size_t)MID * MID, STh, STl, (size_t)PB,
                                  nullptr, cfr, PB, 0, MID, MID, NPIX, 1.0f, 1);

    // --- 0: fuse + final conv
    cudaStreamWaitEvent(0, ev[4], 0);
    fuseT_kernel<<<gT, bT>>>(Qch, Qcl, cfr, V, Fw, lambd, beta, fuTh, fuTl);
    mma_gemm<<<gN, 256, G_SMEM>>>(owh, owl, 0, fuTh, fuTl, (size_t)PB,
                                  out_b, (float*)d_out, PB, 0, MID, MID, NPIX, 1.0f, 1);
}

// round 15
// speedup vs baseline: 1.0327x; 1.0001x over previous
#include <cuda_runtime.h>
#include <cuda_bf16.h>
#include <math.h>
#include <stdint.h>

#define BSZ   8
#define C1    256
#define C2    128
#define MID   256
#define NPIX  4096
#define PB    (MID*NPIX)
#define TOT   ((size_t)BSZ*PB)
#define DD    32
#define NSPLIT 8
#define HROWS 33
#define HSZ   (HROWS * 64)

__device__ __forceinline__ uint32_t smem_u32(const void* p) {
    uint32_t a;
    asm("{ .reg .u64 t; cvta.to.shared.u64 t, %1; cvt.u32.u64 %0, t; }" : "=r"(a) : "l"(p));
    return a;
}

#define CP16(sa, ga) \
    asm volatile("cp.async.ca.shared.global [%0], [%1], 16;" :: "r"(sa), "l"(ga) : "memory")
#define CP_COMMIT() asm volatile("cp.async.commit_group;" ::: "memory")
#define CP_WAIT1()  asm volatile("cp.async.wait_group 1;" ::: "memory")

#define LDSM4(r0, r1, r2, r3, a) \
    asm volatile("ldmatrix.sync.aligned.m8n8.x4.shared.b16 {%0,%1,%2,%3}, [%4];" \
        : "=r"(r0), "=r"(r1), "=r"(r2), "=r"(r3) : "r"(a))

#define MMA16816(c, a, b0, b1) \
    asm volatile("mma.sync.aligned.m16n8k16.row.col.f32.bf16.bf16.f32 " \
        "{%0,%1,%2,%3}, {%4,%5,%6,%7}, {%8,%9}, {%0,%1,%2,%3};" \
        : "+f"((c)[0]), "+f"((c)[1]), "+f"((c)[2]), "+f"((c)[3]) \
        : "r"((a)[0]), "r"((a)[1]), "r"((a)[2]), "r"((a)[3]), "r"(b0), "r"(b1))

__device__ float g_pool[22ull * TOT];

struct Aux {
    cudaStream_t s1, s2;
    cudaEvent_t ev[10];
    Aux() {
        cudaStreamCreateWithFlags(&s1, cudaStreamNonBlocking);
        cudaStreamCreateWithFlags(&s2, cudaStreamNonBlocking);
        for (int i = 0; i < 10; ++i)
            cudaEventCreateWithFlags(&ev[i], cudaEventDisableTiming);
    }
};
static Aux g_aux;

// ---------------------------------------------------------------------------
// Split-bf16 tensor-core GEMM:  Y = scale*(A @ B^T) + bias
// ---------------------------------------------------------------------------
#define ST_BYTES 49152
#define G_SMEM   (3 * ST_BYTES)

__global__ __launch_bounds__(256, 1)
void mma_gemm(const __nv_bfloat16* __restrict__ Ah, const __nv_bfloat16* __restrict__ Al,
              size_t aStride,
              const __nv_bfloat16* __restrict__ Bh, const __nv_bfloat16* __restrict__ Bl,
              size_t bStride,
              const float* __restrict__ bias, float* __restrict__ Y,
              size_t yStride, size_t partStride,
              int Kstride, int Klen, int N, float scale, int NS)
{
    extern __shared__ __nv_bfloat16 dynsm[];
    const uint32_t smBase = smem_u32(dynsm);
    const int t = threadIdx.x, wid = t >> 5, lid = t & 31;
    const int wm = wid & 1, wn = wid >> 1;
    const int z = blockIdx.z;
    const int b = z / NS, s = z % NS;
    const int kBeg = s * Klen;
    const int m0 = blockIdx.y * 128, n0 = blockIdx.x * 256;

    const __nv_bfloat16* P[4];
    P[0] = Ah + (size_t)b * aStride + (size_t)m0 * Kstride + kBeg;
    P[1] = Al + (size_t)b * aStride + (size_t)m0 * Kstride + kBeg;
    P[2] = Bh + (size_t)b * bStride + (size_t)n0 * Kstride + kBeg;
    P[3] = Bl + (size_t)b * bStride + (size_t)n0 * Kstride + kBeg;
    float* Yp = Y + (size_t)b * yStride + (size_t)s * partStride;

    const int NC = Klen >> 5;

    int lrow[4], lc[4]; uint32_t lso[4];
#pragma unroll
    for (int r = 0; r < 4; ++r) {
        int q = t + 256 * r;
        lrow[r] = q >> 2; lc[r] = q & 3;
        lso[r] = lrow[r] * 64 + ((lc[r] ^ ((lrow[r] >> 1) & 3)) * 16);
    }

    const int lj = lid >> 3, lr = lid & 7;
    uint32_t aAddr[4], bAddr[4];
#pragma unroll
    for (int i = 0; i < 4; ++i) {
        int row = wm * 64 + i * 16 + ((lj & 1) << 3) + lr;
        int c = (lj >> 1) ^ ((row >> 1) & 3);
        aAddr[i] = smBase + row * 64 + c * 16;
    }
#pragma unroll
    for (int p = 0; p < 4; ++p) {
        int n = wn * 64 + p * 16 + ((lj >> 1) << 3) + lr;
        int c = (lj & 1) ^ ((n >> 1) & 3);
        bAddr[p] = smBase + 16384 + n * 64 + c * 16;
    }

    float acc[4][8][4];
#pragma unroll
    for (int i = 0; i < 4; ++i)
#pragma unroll
        for (int j = 0; j < 8; ++j)
#pragma unroll
            for (int e = 0; e < 4; ++e) acc[i][j][e] = 0.f;

#define LOADSTAGE(CH, SLOT) do {                                              \
        int kc_ = (CH) << 5;                                                  \
        uint32_t so_ = (uint32_t)(SLOT) * ST_BYTES;                           \
        _Pragma("unroll")                                                     \
        for (int pl_ = 0; pl_ < 2; ++pl_) {                                   \
            const __nv_bfloat16* src_ = P[pl_] + kc_;                         \
            uint32_t dst_ = smBase + so_ + pl_ * 8192;                        \
            _Pragma("unroll")                                                 \
            for (int r_ = 0; r_ < 2; ++r_)                                    \
                CP16(dst_ + lso[r_], src_ + (size_t)lrow[r_] * Kstride + lc[r_] * 8); \
        }                                                                     \
        _Pragma("unroll")                                                     \
        for (int pl_ = 2; pl_ < 4; ++pl_) {                                   \
            const __nv_bfloat16* src_ = P[pl_] + kc_;                         \
            uint32_t dst_ = smBase + so_ + 16384 + (pl_ - 2) * 16384;         \
            _Pragma("unroll")                                                 \
            for (int r_ = 0; r_ < 4; ++r_)                                    \
                CP16(dst_ + lso[r_], src_ + (size_t)lrow[r_] * Kstride + lc[r_] * 8); \
        }                                                                     \
    } while (0)

    LOADSTAGE(0, 0); CP_COMMIT();
    LOADSTAGE(1, 1); CP_COMMIT();

    for (int ch = 0; ch < NC; ++ch) {
        CP_WAIT1();
        __syncthreads();
        int nxt = ch + 2;
        if (nxt < NC) LOADSTAGE(nxt, nxt % 3);
        CP_COMMIT();

        const uint32_t stoff = (uint32_t)(ch % 3) * ST_BYTES;
#pragma unroll
        for (int kt = 0; kt < 2; ++kt) {
            const uint32_t kx = kt ? 32u : 0u;
            uint32_t aH[4][4], bH[4][4], aL[4][4], bL[4][4];
#pragma unroll
            for (int i = 0; i < 4; ++i)
                LDSM4(aH[i][0], aH[i][1], aH[i][2], aH[i][3], (aAddr[i] + stoff) ^ kx);
#pragma unroll
            for (int p = 0; p < 4; ++p)
                LDSM4(bH[p][0], bH[p][1], bH[p][2], bH[p][3], (bAddr[p] + stoff) ^ kx);
#pragma unroll
            for (int i = 0; i < 4; ++i)
                LDSM4(aL[i][0], aL[i][1], aL[i][2], aL[i][3], (aAddr[i] + stoff + 8192) ^ kx);
#pragma unroll
            for (int p = 0; p < 4; ++p)
                LDSM4(bL[p][0], bL[p][1], bL[p][2], bL[p][3], (bAddr[p] + stoff + 16384) ^ kx);
#pragma unroll
            for (int i = 0; i < 4; ++i)
#pragma unroll
                for (int j = 0; j < 8; ++j)
                    MMA16816(acc[i][j], aH[i], bH[j >> 1][(j & 1) * 2], bH[j >> 1][(j & 1) * 2 + 1]);
#pragma unroll
            for (int i = 0; i < 4; ++i)
#pragma unroll
                for (int j = 0; j < 8; ++j)
                    MMA16816(acc[i][j], aL[i], bH[j >> 1][(j & 1) * 2], bH[j >> 1][(j & 1) * 2 + 1]);
#pragma unroll
            for (int i = 0; i < 4; ++i)
#pragma unroll
                for (int j = 0; j < 8; ++j)
                    MMA16816(acc[i][j], aH[i], bL[j >> 1][(j & 1) * 2], bL[j >> 1][(j & 1) * 2 + 1]);
        }
    }
#undef LOADSTAGE

    const int groupID = lid >> 2, tid4 = lid & 3;
#pragma unroll
    for (int i = 0; i < 4; ++i) {
        int r0 = m0 + wm * 64 + i * 16 + groupID;
        int r1 = r0 + 8;
        float bv0 = bias ? bias[r0] : 0.f;
        float bv1 = bias ? bias[r1] : 0.f;
        float* y0 = Yp + (size_t)r0 * N + n0 + wn * 64 + tid4 * 2;
        float* y1 = Yp + (size_t)r1 * N + n0 + wn * 64 + tid4 * 2;
#pragma unroll
        for (int j = 0; j < 8; ++j) {
            *(float2*)(y0 + j * 8) = make_float2(fmaf(acc[i][j][0], scale, bv0),
                                                 fmaf(acc[i][j][1], scale, bv0));
            *(float2*)(y1 + j * 8) = make_float2(fmaf(acc[i][j][2], scale, bv1),
                                                 fmaf(acc[i][j][3], scale, bv1));
        }
    }
}

// ---------------------------------------------------------------------------
// Radix-8x8 FFT machinery
// ---------------------------------------------------------------------------
__device__ __forceinline__ float2 cmulf(float2 a, float2 b) {
    return make_float2(a.x * b.x - a.y * b.y, a.x * b.y + a.y * b.x);
}

template<int S>
__device__ __forceinline__ void fft8(float2 v[8])
{
    const float C0 = 0.70710678118654752f;
    const float SG = (float)S;
    float2 a0 = make_float2(v[0].x + v[4].x, v[0].y + v[4].y);
    float2 a1 = make_float2(v[1].x + v[5].x, v[1].y + v[5].y);
    float2 a2 = make_float2(v[2].x + v[6].x, v[2].y + v[6].y);
    float2 a3 = make_float2(v[3].x + v[7].x, v[3].y + v[7].y);
    float2 b0 = make_float2(v[0].x - v[4].x, v[0].y - v[4].y);
    float2 b1 = make_float2(v[1].x - v[5].x, v[1].y - v[5].y);
    float2 b2 = make_float2(v[2].x - v[6].x, v[2].y - v[6].y);
    float2 b3 = make_float2(v[3].x - v[7].x, v[3].y - v[7].y);
    float2 t1 = make_float2(C0 * (b1.x - SG * b1.y), C0 * (SG * b1.x + b1.y));
    float2 t2 = make_float2(-SG * b2.y, SG * b2.x);
    float2 t3 = make_float2(C0 * (-b3.x - SG * b3.y), C0 * (SG * b3.x - b3.y));
    float2 c0 = make_float2(a0.x + a2.x, a0.y + a2.y);
    float2 c1 = make_float2(a1.x + a3.x, a1.y + a3.y);
    float2 d0 = make_float2(a0.x - a2.x, a0.y - a2.y);
    float2 e0 = make_float2(a1.x - a3.x, a1.y - a3.y);
    float2 d1 = make_float2(-SG * e0.y, SG * e0.x);
    float2 c2 = make_float2(b0.x + t2.x, b0.y + t2.y);
    float2 c3 = make_float2(t1.x + t3.x, t1.y + t3.y);
    float2 d2 = make_float2(b0.x - t2.x, b0.y - t2.y);
    float2 e1 = make_float2(t1.x - t3.x, t1.y - t3.y);
    float2 d3 = make_float2(-SG * e1.y, SG * e1.x);
    v[0] = make_float2(c0.x + c1.x, c0.y + c1.y);
    v[1] = make_float2(c2.x + c3.x, c2.y + c3.y);
    v[2] = make_float2(d0.x + d1.x, d0.y + d1.y);
    v[3] = make_float2(d2.x + d3.x, d2.y + d3.y);
    v[4] = make_float2(c0.x - c1.x, c0.y - c1.y);
    v[5] = make_float2(c2.x - c3.x, c2.y - c3.y);
    v[6] = make_float2(d0.x - d1.x, d0.y - d1.y);
    v[7] = make_float2(d2.x - d3.x, d2.y - d3.y);
}

template<int S>
__device__ __forceinline__ void fftpass(float2* bin, float2* bout, const float2* tw, int t)
{
    const int r = t >> 2, q = t & 3;
    const int rb = r * 65;
    float2 g[2][8];
#pragma unroll
    for (int gi = 0; gi < 2; ++gi) {
        int bcol = q + 4 * gi;
#pragma unroll
        for (int a = 0; a < 8; ++a) g[gi][a] = bin[rb + 8 * a + bcol];
        fft8<S>(g[gi]);
#pragma unroll
        for (int k1 = 0; k1 < 8; ++k1) g[gi][k1] = cmulf(g[gi][k1], tw[bcol * 8 + k1]);
    }
#pragma unroll
    for (int gi = 0; gi < 2; ++gi) {
        int bcol = q + 4 * gi;
#pragma unroll
        for (int k1 = 0; k1 < 8; ++k1) bin[rb + k1 * 8 + bcol] = g[gi][k1];
    }
    __syncwarp();
#pragma unroll
    for (int gi = 0; gi < 2; ++gi) {
        int k1 = q + 4 * gi;
        float2 h[8];
#pragma unroll
        for (int bcol = 0; bcol < 8; ++bcol) h[bcol] = bin[rb + k1 * 8 + bcol];
        fft8<S>(h);
#pragma unroll
        for (int k2 = 0; k2 < 8; ++k2) bout[(k1 + 8 * k2) * 65 + r] = h[k2];
    }
}

#define FFT_SMEM ((2 * 64 * 65 + 64) * 8)
#define DW_SMEM  (FFT_SMEM + 64 * 65 * 4)

__global__ void fft2_dw_kernel(const float* __restrict__ pre, size_t preStride,
                               const float* __restrict__ wt, const float* __restrict__ bs,
                               __nv_bfloat16* __restrict__ oh, __nv_bfloat16* __restrict__ ol,
                               int rev, float2* __restrict__ Xout)
{
    extern __shared__ float2 fsm[];
    float2* bufA = fsm;
    float2* bufB = fsm + 64 * 65;
    float2* tw   = fsm + 2 * 64 * 65;
    float*  xin  = (float*)(fsm + 2 * 64 * 65 + 64);
    int t = threadIdx.x;
    int img = blockIdx.x;
    int c = img & 255;
    if (t < 64) {
        int bcol = t >> 3, k1 = t & 7;
        float sn, cs; sincospif(-(float)(bcol * k1) / 32.0f, &sn, &cs);
        tw[t] = make_float2(cs, sn);
    }
    const float* xi = pre + (size_t)(img >> 8) * preStride + ((size_t)c << 12);
    for (int i = t; i < 4096; i += 256) xin[(i >> 6) * 65 + (i & 63)] = xi[i];
    const float* wp = wt + c * 9;
    float k0 = wp[0], k1 = wp[1], k2 = wp[2], k3 = wp[3], k4 = wp[4],
          k5 = wp[5], k6 = wp[6], k7 = wp[7], k8 = wp[8];
    float bv = bs[c];
    __syncthreads();
    for (int i = t; i < 4096; i += 256) {
        int h = i >> 6, w = i & 63;
        const float* row = xin + h * 65;
        float s = bv + k4 * row[w];
        bool ht = h > 0, hb = h < 63, wl = w > 0, wr = w < 63;
        if (ht) {
            const float* ru = row - 65;
            s += k1 * ru[w];
            if (wl) s += k0 * ru[w - 1];
            if (wr) s += k2 * ru[w + 1];
        }
        if (wl) s += k3 * row[w - 1];
        if (wr) s += k5 * row[w + 1];
        if (hb) {
            const float* rd = row + 65;
            s += k7 * rd[w];
            if (wl) s += k6 * rd[w - 1];
            if (wr) s += k8 * rd[w + 1];
        }
        bufA[h * 65 + w] = make_float2(s, 0.f);
        if (oh) {
            size_t base = (size_t)img << 12;
            int oi = rev ? ((((64 - h) & 63) << 6) | ((64 - w) & 63)) : i;
            __nv_bfloat16 hh = __float2bfloat16(s);
            oh[base + oi] = hh;
            ol[base + oi] = __float2bfloat16(s - __bfloat162float(hh));
        }
    }
    __syncthreads();
    fftpass<-1>(bufA, bufB, tw, t);
    __syncthreads();
    fftpass<-1>(bufB, bufA, tw, t);
    __syncthreads();
    float2* o = Xout + (size_t)blockIdx.x * HSZ;
    for (int i = t; i < HSZ; i += 256)
        o[i] = bufA[(i >> 6) * 65 + (i & 63)];
}

__global__ void ifft2_prod_kernel(const float2* __restrict__ FQ, const float2* __restrict__ FK,
                                  float* __restrict__ out)
{
    extern __shared__ float2 fsm[];
    float2* bufA = fsm;
    float2* bufB = fsm + 64 * 65;
    float2* tw   = fsm + 2 * 64 * 65;
    int t = threadIdx.x;
    if (t < 64) {
        int bcol = t >> 3, k1 = t & 7;
        float sn, cs; sincospif((float)(bcol * k1) / 32.0f, &sn, &cs);
        tw[t] = make_float2(cs, sn);
    }
    const float2* q = FQ + (size_t)blockIdx.x * HSZ;
    const float2* kk = FK + (size_t)blockIdx.x * HSZ;
    for (int i = t; i < HSZ; i += 256) {
        float2 a = q[i], b = kk[i];
        bufA[(i >> 6) * 65 + (i & 63)] =
            make_float2(a.x * b.x - a.y * b.y, a.x * b.y + a.y * b.x);
    }
    __syncthreads();
    for (int i = t; i < 31 * 64; i += 256) {
        int u = 33 + (i >> 6), v = i & 63;
        float2 m = bufA[(64 - u) * 65 + ((64 - v) & 63)];
        bufA[u * 65 + v] = make_float2(m.x, -m.y);
    }
    __syncthreads();
    fftpass<1>(bufA, bufB, tw, t);
    __syncthreads();
    fftpass<1>(bufB, bufA, tw, t);
    __syncthreads();
    float* o = out + (size_t)blockIdx.x * 4096;
    for (int i = t; i < 4096; i += 256)
        o[i] = bufA[(i >> 6) * 65 + (i & 63)].x * (1.0f / 4096.0f);
}

// ---------------------------------------------------------------------------
__global__ void convW_kernel(
    const float* __restrict__ wr, const float* __restrict__ wn,
    const float* __restrict__ pq, const float* __restrict__ pk, const float* __restrict__ pv,
    const float* __restrict__ ow,
    const float* __restrict__ pqb, const float* __restrict__ pkb, const float* __restrict__ pvb,
    __nv_bfloat16* wrh, __nv_bfloat16* wrl, __nv_bfloat16* wnh, __nv_bfloat16* wnl,
    __nv_bfloat16* wqh, __nv_bfloat16* wql, __nv_bfloat16* owh, __nv_bfloat16* owl,
    float* qkvb)
{
    int i = blockIdx.x * 256 + threadIdx.x;
    if (i < 65536) {
        float x = wr[i]; __nv_bfloat16 h = __float2bfloat16(x);
        wrh[i] = h; wrl[i] = __float2bfloat16(x - __bfloat162float(h));
    } else if (i < 98304) {
        int j = i - 65536;
        float x = wn[j]; __nv_bfloat16 h = __float2bfloat16(x);
        wnh[j] = h; wnl[j] = __float2bfloat16(x - __bfloat162float(h));
    } else if (i < 294912) {
        int j = i - 98304;
        const float* s3 = (j < 65536) ? pq : (j < 131072) ? pk : pv;
        float x = s3[j & 65535]; __nv_bfloat16 h = __float2bfloat16(x);
        wqh[j] = h; wql[j] = __float2bfloat16(x - __bfloat162float(h));
    } else if (i < 360448) {
        int j = i - 294912;
        float x = ow[j]; __nv_bfloat16 h = __float2bfloat16(x);
        owh[j] = h; owl[j] = __float2bfloat16(x - __bfloat162float(h));
    } else if (i < 361216) {
        int j = i - 360448;
        qkvb[j] = (j < 256) ? pqb[j] : (j < 512) ? pkb[j - 256] : pvb[j - 512];
    }
}

// packed-store transpose: fp32 [R][C] -> split-bf16 [C][R], 2 bf16 per STG.32
__global__ void convT_kernel(const float* __restrict__ in,
                             __nv_bfloat16* __restrict__ oh, __nv_bfloat16* __restrict__ ol,
                             int R, int C)
{
    __shared__ float tile[32][33];
    int b = blockIdx.z;
    const float* ip = in + (size_t)b * R * C;
    uint32_t* ohp = (uint32_t*)(oh + (size_t)b * R * C);
    uint32_t* olp = (uint32_t*)(ol + (size_t)b * R * C);
    int c0 = blockIdx.x * 32, r0 = blockIdx.y * 32;
    int tx = threadIdx.x, ty = threadIdx.y;   // (16,16)
#pragma unroll
    for (int j = 0; j < 2; ++j) {
        int row = ty + 16 * j;
        float2 v = *(const float2*)&ip[(size_t)(r0 + row) * C + c0 + 2 * tx];
        tile[row][2 * tx]     = v.x;
        tile[row][2 * tx + 1] = v.y;
    }
    __syncthreads();
#pragma unroll
    for (int j = 0; j < 2; ++j) {
        int cc = ty + 16 * j;
        float a = tile[2 * tx][cc], bv = tile[2 * tx + 1][cc];
        __nv_bfloat16 ha = __float2bfloat16(a), hb = __float2bfloat16(bv);
        __nv_bfloat16 la = __float2bfloat16(a - __bfloat162float(ha));
        __nv_bfloat16 lb = __float2bfloat16(bv - __bfloat162float(hb));
        size_t o = ((size_t)(c0 + cc) * R + r0 + 2 * tx) >> 1;
        ohp[o] = ((uint32_t)__bfloat16_as_ushort(hb) << 16) | __bfloat16_as_ushort(ha);
        olp[o] = ((uint32_t)__bfloat16_as_ushort(lb) << 16) | __bfloat16_as_ushort(la);
    }
}

// ---------------------------------------------------------------------------
__global__ void meanX_kernel(const float* __restrict__ x1, const float* __restrict__ x2,
                             float* __restrict__ m1, float* __restrict__ m2)
{
    __shared__ float red[256];
    int img = blockIdx.x, t = threadIdx.x;
    const float* src; float* dst; int idx;
    if (img < BSZ * C1) { src = x1 + (size_t)img * NPIX; dst = m1; idx = img; }
    else { idx = img - BSZ * C1; src = x2 + (size_t)idx * NPIX; dst = m2; }
    float s = 0.f;
    for (int i = t; i < NPIX; i += 256) s += src[i];
    red[t] = s; __syncthreads();
    for (int st = 128; st > 0; st >>= 1) {
        if (t < st) red[t] += red[t + st];
        __syncthreads();
    }
    if (t == 0) dst[idx] = red[0] * (1.0f / NPIX);
}

__global__ void pooledmlp_kernel(const float* __restrict__ m1, const float* __restrict__ m2,
                                 const float* __restrict__ wr, const float* __restrict__ br,
                                 const float* __restrict__ wn, const float* __restrict__ bn,
                                 const float* __restrict__ w1, const float* __restrict__ w2,
                                 float* __restrict__ a0out, float* __restrict__ a1out)
{
    __shared__ float pooled[MID];
    __shared__ float hs[DD];
    int b = blockIdx.x, t = threadIdx.x;
    {
        int c = t;
        float s = br[c] + bn[c];
        const float* wrow = wr + c * C1;
        const float* m1b = m1 + b * C1;
#pragma unroll 8
        for (int i = 0; i < C1; ++i) s += wrow[i] * m1b[i];
        const float* nrow = wn + c * C2;
        const float* m2b = m2 + b * C2;
#pragma unroll 8
        for (int j = 0; j < C2; ++j) s += nrow[j] * m2b[j];
        pooled[c] = s;
    }
    __syncthreads();
    {
        int d = t >> 3, ln = t & 7;
        float s = 0.f;
        for (int c = ln; c < MID; c += 8) s += pooled[c] * w1[d * MID + c];
#pragma unroll
        for (int k = 4; k > 0; k >>= 1) s += __shfl_down_sync(0xffffffffu, s, k, 8);
        if (ln == 0) hs[d] = fmaxf(s, 0.f);
    }
    __syncthreads();
    {
        int c = t;
        float a0 = 0.f, a1 = 0.f;
#pragma unroll
        for (int d = 0; d < DD; ++d) {
            float hv = hs[d];
            a0 += hv * w2[c * DD + d];
            a1 += hv * w2[(MID + c) * DD + d];
        }
        float m = fmaxf(a0, a1);
        float e0 = expf(a0 - m), e1 = expf(a1 - m);
        float inv = 1.0f / (e0 + e1);
        a0out[b * MID + c] = e0 * inv;
        a1out[b * MID + c] = e1 * inv;
    }
}

// blend: writes ONLY transposed split-bf16 (no fp32 Fw)
__global__ void blendT_kernel(const float* __restrict__ FR, const float* __restrict__ FN,
                              const float* __restrict__ w0, const float* __restrict__ w1,
                              __nv_bfloat16* __restrict__ oh, __nv_bfloat16* __restrict__ ol)
{
    __shared__ float tile[32][33];
    int b = blockIdx.z;
    int p0 = blockIdx.x * 32, c0 = blockIdx.y * 32;
    int tx = threadIdx.x, ty = threadIdx.y;
#pragma unroll
    for (int j = 0; j < 4; ++j) {
        int c = c0 + ty + 8 * j;
        size_t idx = (size_t)b * PB + (size_t)c * NPIX + p0 + tx;
        tile[ty + 8 * j][tx] = w0[b * MID + c] * FR[idx] + w1[b * MID + c] * FN[idx];
    }
    __syncthreads();
#pragma unroll
    for (int j = 0; j < 4; ++j) {
        float x = tile[tx][ty + 8 * j];
        __nv_bfloat16 h = __float2bfloat16(x);
        size_t o = (size_t)b * PB + (size_t)(p0 + ty + 8 * j) * MID + c0 + tx;
        oh[o] = h;
        ol[o] = __float2bfloat16(x - __bfloat162float(h));
    }
}

__global__ void dwconv3x3_kernel(const float* __restrict__ x, size_t preStride,
                                 const float* __restrict__ wt,
                                 const float* __restrict__ bs, float* __restrict__ y)
{
    __shared__ float xs[64][65];
    int img = blockIdx.x;
    int c = img & 255;
    const float* xi = x + (size_t)(img >> 8) * preStride + ((size_t)c << 12);
    for (int i = threadIdx.x; i < NPIX; i += 256) xs[i >> 6][i & 63] = xi[i];
    const float* wp = wt + c * 9;
    float k0 = wp[0], k1 = wp[1], k2 = wp[2], k3 = wp[3], k4 = wp[4],
          k5 = wp[5], k6 = wp[6], k7 = wp[7], k8 = wp[8];
    float bv = bs[c];
    __syncthreads();
    for (int i = threadIdx.x; i < NPIX; i += 256) {
        int h = i >> 6, w = i & 63;
        float s = bv + k4 * xs[h][w];
        bool ht = h > 0, hb = h < 63, wl = w > 0, wr = w < 63;
        if (ht) {
            s += k1 * xs[h - 1][w];
            if (wl) s += k0 * xs[h - 1][w - 1];
            if (wr) s += k2 * xs[h - 1][w + 1];
        }
        if (wl) s += k3 * xs[h][w - 1];
        if (wr) s += k5 * xs[h][w + 1];
        if (hb) {
            s += k7 * xs[h + 1][w];
            if (wl) s += k6 * xs[h + 1][w - 1];
            if (wr) s += k8 * xs[h + 1][w + 1];
        }
        y[((size_t)img << 12) + i] = s;
    }
}

__global__ void softmax_kernel(const float* __restrict__ attnP,
                               __nv_bfloat16* __restrict__ ah, __nv_bfloat16* __restrict__ al,
                               const float* __restrict__ alpha)
{
    __shared__ float red[256];
    int row = blockIdx.x, t = threadIdx.x;
    float v = 0.f;
#pragma unroll
    for (int s = 0; s < NSPLIT; ++s)
        v += attnP[(size_t)s * (BSZ * 65536) + (size_t)row * 256 + t];
    float inva = 1.0f / (*alpha);
    v = fabsf(v) * inva;
    red[t] = v; __syncthreads();
    for (int s = 128; s > 0; s >>= 1) {
        if (t < s) red[t] = fmaxf(red[t], red[t + s]);
        __syncthreads();
    }
    float m = red[0]; __syncthreads();
    float e = expf(v - m);
    red[t] = e; __syncthreads();
    for (int s = 128; s > 0; s >>= 1) {
        if (t < s) red[t] += red[t + s];
        __syncthreads();
    }
    float val = e / red[0];
    __nv_bfloat16 h = __float2bfloat16(val);
    ah[(size_t)row * 256 + t] = h;
    al[(size_t)row * 256 + t] = __float2bfloat16(val - __bfloat162float(h));
}

// fused output; Q and Fw reconstructed from their split-bf16 planes.
// Fw comes from the TRANSPOSED planes (FwTh/FwTl, layout [p][c]).
__global__ void fuseT_kernel(const __nv_bfloat16* __restrict__ Qh,
                             const __nv_bfloat16* __restrict__ Ql,
                             const float* __restrict__ cfr,
                             const float* __restrict__ V,
                             const __nv_bfloat16* __restrict__ FwTh,
                             const __nv_bfloat16* __restrict__ FwTl,
                             const float* __restrict__ lambd, const float* __restrict__ beta,
                             __nv_bfloat16* __restrict__ oh, __nv_bfloat16* __restrict__ ol)
{
    __shared__ float tile[32][33];
    __shared__ float tileF[32][33];           // [p_local][c_local]
    int b = blockIdx.z;
    int p0 = blockIdx.x * 32, c0 = blockIdx.y * 32;
    int tx = threadIdx.x, ty = threadIdx.y;
    float l = *lambd, be = *beta;
    // load Fw tile from transposed planes (coalesced in c)
#pragma unroll
    for (int j = 0; j < 4; ++j) {
        int pl = ty + 8 * j;
        size_t o = (size_t)b * PB + (size_t)(p0 + pl) * MID + c0 + tx;
        tileF[pl][tx] = __bfloat162float(FwTh[o]) + __bfloat162float(FwTl[o]);
    }
    __syncthreads();
#pragma unroll
    for (int j = 0; j < 4; ++j) {
        size_t idx = (size_t)b * PB + (size_t)(c0 + ty + 8 * j) * NPIX + p0 + tx;
        float q = __bfloat162float(Qh[idx]) + __bfloat162float(Ql[idx]);
        float c = cfr[idx], v = V[idx];
        float f = tileF[tx][ty + 8 * j];
        float freq_out = q * c + v - l * v * c;
        tile[ty + 8 * j][tx] = be * freq_out + (1.0f - be) * f;
    }
    __syncthreads();
#pragma unroll
    for (int j = 0; j < 4; ++j) {
        float x = tile[tx][ty + 8 * j];
        __nv_bfloat16 h = __float2bfloat16(x);
        size_t o = (size_t)b * PB + (size_t)(p0 + ty + 8 * j) * MID + c0 + tx;
        oh[o] = h;
        ol[o] = __float2bfloat16(x - __bfloat162float(h));
    }
}

// ---------------------------------------------------------------------------
extern "C" void kernel_launch(void* const* d_in, const int* in_sizes, int n_in,
                              void* d_out, int out_size)
{
    const float* x1       = (const float*)d_in[0];
    const float* x2       = (const float*)d_in[1];
    const float* conv_r_w = (const float*)d_in[2];
    const float* conv_r_b = (const float*)d_in[3];
    const float* conv_n_w = (const float*)d_in[4];
    const float* conv_n_b = (const float*)d_in[5];
    const float* mlp_w1   = (const float*)d_in[6];
    const float* mlp_w2   = (const float*)d_in[7];
    const float* pq_w     = (const float*)d_in[8];
    const float* pq_b     = (const float*)d_in[9];
    const float* dq_w     = (const float*)d_in[10];
    const float* dq_b     = (const float*)d_in[11];
    const float* pk_w     = (const float*)d_in[12];
    const float* pk_b     = (const float*)d_in[13];
    const float* dk_w     = (const float*)d_in[14];
    const float* dk_b     = (const float*)d_in[15];
    const float* pv_w     = (const float*)d_in[16];
    const float* pv_b     = (const float*)d_in[17];
    const float* dv_w     = (const float*)d_in[18];
    const float* dv_b     = (const float*)d_in[19];
    const float* out_w    = (const float*)d_in[20];
    const float* out_b    = (const float*)d_in[21];
    const float* alpha    = (const float*)d_in[22];
    const float* lambd    = (const float*)d_in[23];
    const float* beta     = (const float*)d_in[24];

    float* pool;
    cudaGetSymbolAddress((void**)&pool, g_pool);
    float*  FR      = pool;
    float*  FN      = pool + 1 * TOT;
    float*  cfr     = pool + 3 * TOT;
    float*  V       = pool + 5 * TOT;
    float*  qkvPre  = pool + 6 * TOT;
    float2* FQ      = (float2*)(pool + 9 * TOT);
    float2* FK      = (float2*)(pool + 11 * TOT);
    float*  S       = pool + 13 * TOT;
    float*  attnP   = pool + 14 * TOT;
    float*  w0      = pool + 15 * TOT;
    float*  w1      = w0 + 2048;
    float*  qkvb    = w1 + 2048;
    float*  m1      = qkvb + 1024;
    float*  m2      = m1 + 2048;

    __nv_bfloat16* bb = (__nv_bfloat16*)(pool + 15 * TOT + 16384);
    __nv_bfloat16* x1Th = bb;              __nv_bfloat16* x1Tl = bb + 1 * TOT;
    __nv_bfloat16* x2Th = bb + 2 * TOT;    __nv_bfloat16* x2Tl = x2Th + TOT / 2;
    __nv_bfloat16* FwTh = bb + 3 * TOT;    __nv_bfloat16* FwTl = bb + 4 * TOT;
    __nv_bfloat16* STh  = bb + 5 * TOT;    __nv_bfloat16* STl  = bb + 6 * TOT;
    __nv_bfloat16* fuTh = bb + 7 * TOT;    __nv_bfloat16* fuTl = bb + 8 * TOT;
    __nv_bfloat16* Qch  = bb + 9 * TOT;    __nv_bfloat16* Qcl  = bb + 10 * TOT;
    __nv_bfloat16* Krh  = bb + 11 * TOT;   __nv_bfloat16* Krl  = bb + 12 * TOT;
    __nv_bfloat16* small = bb + 13 * TOT;
    __nv_bfloat16* ach  = small;             __nv_bfloat16* acl  = ach + 524288;
    __nv_bfloat16* wrh  = acl + 524288;      __nv_bfloat16* wrl  = wrh + 65536;
    __nv_bfloat16* wnh  = wrl + 65536;       __nv_bfloat16* wnl  = wnh + 32768;
    __nv_bfloat16* wqh  = wnl + 32768;       __nv_bfloat16* wql  = wqh + 196608;
    __nv_bfloat16* owh  = wql + 196608;      __nv_bfloat16* owl  = owh + 65536;

    cudaFuncSetAttribute(mma_gemm, cudaFuncAttributeMaxDynamicSharedMemorySize, G_SMEM);
    cudaFuncSetAttribute(fft2_dw_kernel, cudaFuncAttributeMaxDynamicSharedMemorySize, DW_SMEM);
    cudaFuncSetAttribute(ifft2_prod_kernel, cudaFuncAttributeMaxDynamicSharedMemorySize, FFT_SMEM);

    cudaStream_t s1 = g_aux.s1, s2 = g_aux.s2;
    cudaEvent_t* ev = g_aux.ev;

    const int NIMG = BSZ * MID;
    const dim3 gN(16, 2, BSZ);
    const dim3 gT(128, 8, BSZ), bT(32, 8);
    const dim3 bT2(16, 16);

    // --- fork event at capture origin (R14 schedule)
    cudaEventRecord(ev[8], 0);

    // --- s2: channel-attention weights from input means
    cudaStreamWaitEvent(s2, ev[8], 0);
    meanX_kernel<<<BSZ * (C1 + C2), 256, 0, s2>>>(x1, x2, m1, m2);
    pooledmlp_kernel<<<BSZ, 256, 0, s2>>>(m1, m2, conv_r_w, conv_r_b, conv_n_w, conv_n_b,
                                          mlp_w1, mlp_w2, w0, w1);
    cudaEventRecord(ev[7], s2);

    // --- stream 0: weights
    convW_kernel<<<1411, 256>>>(conv_r_w, conv_n_w, pq_w, pk_w, pv_w, out_w,
                                pq_b, pk_b, pv_b,
                                wrh, wrl, wnh, wnl, wqh, wql, owh, owl, qkvb);
    cudaEventRecord(ev[0], 0);

    // --- s1: x2 chain
    cudaStreamWaitEvent(s1, ev[0], 0);
    convT_kernel<<<dim3(128, 4, BSZ), bT2, 0, s1>>>(x2, x2Th, x2Tl, C2, NPIX);
    mma_gemm<<<gN, 256, G_SMEM, s1>>>(wnh, wnl, 0, x2Th, x2Tl, (size_t)NPIX * C2,
                                      conv_n_b, FN, PB, 0, C2, C2, NPIX, 1.0f, 1);
    cudaEventRecord(ev[1], s1);

    // --- stream 0: x1 chain
    convT_kernel<<<dim3(128, 8, BSZ), bT2>>>(x1, x1Th, x1Tl, C1, NPIX);
    mma_gemm<<<gN, 256, G_SMEM>>>(wrh, wrl, 0, x1Th, x1Tl, (size_t)NPIX * C1,
                                  conv_r_b, FR, PB, 0, C1, C1, NPIX, 1.0f, 1);
    cudaStreamWaitEvent(0, ev[1], 0);
    cudaStreamWaitEvent(0, ev[7], 0);

    // --- blend (split-bf16 transposed only; no fp32 Fw)
    blendT_kernel<<<gT, bT>>>(FR, FN, w0, w1, FwTh, FwTl);

    // --- merged QKV pre-convs
    mma_gemm<<<dim3(16, 6, BSZ), 256, G_SMEM>>>(wqh, wql, 0, FwTh, FwTl, (size_t)PB,
                                                qkvb, qkvPre, 3 * (size_t)PB, 0,
                                                MID, MID, NPIX, 1.0f, 1);
    cudaEventRecord(ev[2], 0);

    // --- s1: K chain; s2: V chain; 0: Q chain
    cudaStreamWaitEvent(s1, ev[2], 0);
    fft2_dw_kernel<<<NIMG, 256, DW_SMEM, s1>>>(qkvPre + PB, 3 * (size_t)PB, dk_w, dk_b,
                                               Krh, Krl, 1, FK);
    cudaEventRecord(ev[3], s1);
    cudaStreamWaitEvent(s2, ev[2], 0);
    dwconv3x3_kernel<<<NIMG, 256, 0, s2>>>(qkvPre + 2 * (size_t)PB, 3 * (size_t)PB,
                                           dv_w, dv_b, V);
    cudaEventRecord(ev[4], s2);
    fft2_dw_kernel<<<NIMG, 256, DW_SMEM>>>(qkvPre, 3 * (size_t)PB, dq_w, dq_b,
                                           Qch, Qcl, 0, FQ);
    cudaEventRecord(ev[5], 0);

    // --- s1: ifft2(FQ.*FK) + transpose (overlaps attn gemm on 0)
    cudaStreamWaitEvent(s1, ev[5], 0);
    ifft2_prod_kernel<<<NIMG, 256, FFT_SMEM, s1>>>(FQ, FK, S);
    convT_kernel<<<dim3(128, 8, BSZ), bT2, 0, s1>>>(S, STh, STl, MID, NPIX);
    cudaEventRecord(ev[6], s1);

    // --- 0: attn gemm (single wave) + softmax
    cudaStreamWaitEvent(0, ev[3], 0);
    mma_gemm<<<dim3(1, 2, BSZ * NSPLIT), 256, G_SMEM>>>(
        Qch, Qcl, (size_t)PB, Krh, Krl, (size_t)PB,
        nullptr, attnP, 65536, (size_t)BSZ * 65536,
        NPIX, NPIX / NSPLIT, MID, 4096.0f, NSPLIT);
    softmax_kernel<<<NIMG, 256>>>(attnP, ach, acl, alpha);

    // --- 0: cfr gemm
    cudaStreamWaitEvent(0, ev[6], 0);
    mma_gemm<<<gN, 256, G_SMEM>>>(ach, acl, (size_t)MID * MID, STh, STl, (size_t)PB,
                                  nullptr, cfr, PB, 0, MID, MID, NPIX, 1.0f, 1);

    // --- 0: fuse + final conv
    cudaStreamWaitEvent(0, ev[4], 0);
    fuseT_kernel<<<gT, bT>>>(Qch, Qcl, cfr, V, FwTh, FwTl, lambd, beta, fuTh, fuTl);
    mma_gemm<<<gN, 256, G_SMEM>>>(owh, owl, 0, fuTh, fuTl, (size_t)PB,
                                  out_b, (float*)d_out, PB, 0, MID, MID, NPIX, 1.0f, 1);
}